// round 3
// baseline (speedup 1.0000x reference)
#include <cuda_runtime.h>
#include <math.h>

#define B_  2
#define S_  2048
#define D_  2048
#define H_  16
#define KV_ 4
#define HD_ 128
#define G_  4

// Scratch (static device globals; no allocation allowed)
__device__ float g_q[(size_t)B_*S_*H_*HD_];    // [B,S,H,HD]
__device__ float g_k[(size_t)B_*S_*KV_*HD_];   // [B,S,KV,HD]
__device__ float g_v[(size_t)B_*S_*KV_*HD_];   // [B,S,KV,HD]
__device__ float g_ctx[(size_t)B_*S_*H_*HD_];  // [B,S,H,HD]

// ---------------------------------------------------------------------------
// C[M,N] = A[M,K] * B[N,K]^T   (both K-major, fp32)
// 128x128 tile, BK=8, 256 threads, 8x8 micro-tile per thread.
// ---------------------------------------------------------------------------
__global__ __launch_bounds__(256) void sgemm_nt(const float* __restrict__ A,
                                                const float* __restrict__ Bm,
                                                float* __restrict__ C,
                                                int M, int N, int K) {
    __shared__ float As[8][128];
    __shared__ float Bs[8][128];
    const int t = threadIdx.x;
    const int rowBase = blockIdx.y * 128;
    const int colBase = blockIdx.x * 128;
    const int ty = t >> 4, tx = t & 15;
    const int lr = t >> 1;          // 0..127
    const int lk = (t & 1) << 2;    // 0 or 4

    const float* Ap = A + (size_t)(rowBase + lr) * K + lk;
    const float* Bp = Bm + (size_t)(colBase + lr) * K + lk;

    float acc[8][8];
#pragma unroll
    for (int i = 0; i < 8; i++)
#pragma unroll
        for (int j = 0; j < 8; j++) acc[i][j] = 0.0f;

    for (int k0 = 0; k0 < K; k0 += 8) {
        float4 a4 = *(const float4*)(Ap + k0);
        float4 b4 = *(const float4*)(Bp + k0);
        As[lk + 0][lr] = a4.x; As[lk + 1][lr] = a4.y;
        As[lk + 2][lr] = a4.z; As[lk + 3][lr] = a4.w;
        Bs[lk + 0][lr] = b4.x; Bs[lk + 1][lr] = b4.y;
        Bs[lk + 2][lr] = b4.z; Bs[lk + 3][lr] = b4.w;
        __syncthreads();
#pragma unroll
        for (int k = 0; k < 8; k++) {
            float a[8], b[8];
#pragma unroll
            for (int i = 0; i < 8; i++) a[i] = As[k][ty * 8 + i];
#pragma unroll
            for (int j = 0; j < 8; j++) b[j] = Bs[k][tx * 8 + j];
#pragma unroll
            for (int i = 0; i < 8; i++)
#pragma unroll
                for (int j = 0; j < 8; j++) acc[i][j] += a[i] * b[j];
        }
        __syncthreads();
    }
#pragma unroll
    for (int i = 0; i < 8; i++) {
        float* Cp = C + (size_t)(rowBase + ty * 8 + i) * N + colBase + tx * 8;
#pragma unroll
        for (int j = 0; j < 8; j++) Cp[j] = acc[i][j];
    }
}

// ---------------------------------------------------------------------------
// Fused RMSNorm + RoPE, in place. One block (128 thr) per (b,s,head) row.
// t layout: [B*S, nh, 128]. cos/sin: [S,128].
// ---------------------------------------------------------------------------
__global__ __launch_bounds__(128) void norm_rope(float* __restrict__ t,
                                                 const float* __restrict__ w,
                                                 const float* __restrict__ cs,
                                                 const float* __restrict__ sn,
                                                 int nh) {
    const int row = blockIdx.x;             // over B*S*nh
    const int s = (row / nh) % S_;
    const int i = threadIdx.x;
    float* p = t + (size_t)row * HD_;
    float v = p[i];
    float ss = v * v;
#pragma unroll
    for (int o = 16; o; o >>= 1) ss += __shfl_xor_sync(0xffffffff, ss, o);
    __shared__ float wsum[4];
    __shared__ float nbuf[HD_];
    if ((i & 31) == 0) wsum[i >> 5] = ss;
    __syncthreads();
    float tot = wsum[0] + wsum[1] + wsum[2] + wsum[3];
    float rstd = rsqrtf(tot * (1.0f / HD_) + 1e-5f);
    float n = v * rstd * w[i];
    nbuf[i] = n;
    __syncthreads();
    float rot = (i < 64) ? -nbuf[i + 64] : nbuf[i - 64];
    p[i] = n * cs[s * HD_ + i] + rot * sn[s * HD_ + i];
}

// ---------------------------------------------------------------------------
// Causal GQA flash attention, fp32. BQ=BK=64, HD=128, 256 threads.
// grid: (S/64, H, B). Dynamic smem ~83.5 KB.
// ---------------------------------------------------------------------------
__global__ __launch_bounds__(256) void flash_attn(const float* __restrict__ q,
                                                  const float* __restrict__ k,
                                                  const float* __restrict__ v,
                                                  float* __restrict__ ctx) {
    extern __shared__ float sm[];
    float* sQ  = sm;               // 64*129
    float* sKV = sQ + 64 * 129;    // 64*129
    float* sS  = sKV + 64 * 129;   // 64*65
    float* sM  = sS + 64 * 65;     // 64
    float* sL  = sM + 64;          // 64
    float* sAl = sL + 64;          // 64

    const int b = blockIdx.z, h = blockIdx.y, qt = blockIdx.x;
    const int kvh = h / G_;
    const int q0 = qt * 64;
    const int t = threadIdx.x;
    const int ty = t >> 4, tx = t & 15;
    const float scale = 0.08838834764831845f;  // 1/sqrt(128)

    // Load Q tile [64,128]
    for (int idx = t; idx < 64 * HD_; idx += 256) {
        int r = idx >> 7, d = idx & 127;
        sQ[r * 129 + d] = q[((size_t)(b * S_ + q0 + r) * H_ + h) * HD_ + d];
    }
    if (t < 64) { sM[t] = -1e30f; sL[t] = 0.0f; }

    float acc[4][8];
#pragma unroll
    for (int i = 0; i < 4; i++)
#pragma unroll
        for (int j = 0; j < 8; j++) acc[i][j] = 0.0f;

    for (int kt = 0; kt <= qt; kt++) {
        __syncthreads();   // protect sKV (prev PV) and first-iter init
        // Load K tile
        for (int idx = t; idx < 64 * HD_; idx += 256) {
            int r = idx >> 7, d = idx & 127;
            sKV[r * 129 + d] = k[((size_t)(b * S_ + kt * 64 + r) * KV_ + kvh) * HD_ + d];
        }
        __syncthreads();
        // S = Q K^T  (each thread: 4x4)
        float sc[4][4];
#pragma unroll
        for (int i = 0; i < 4; i++)
#pragma unroll
            for (int j = 0; j < 4; j++) sc[i][j] = 0.0f;
        for (int d = 0; d < HD_; d++) {
            float a[4], bb[4];
#pragma unroll
            for (int i = 0; i < 4; i++) a[i] = sQ[(ty * 4 + i) * 129 + d];
#pragma unroll
            for (int j = 0; j < 4; j++) bb[j] = sKV[(tx * 4 + j) * 129 + d];
#pragma unroll
            for (int i = 0; i < 4; i++)
#pragma unroll
                for (int j = 0; j < 4; j++) sc[i][j] += a[i] * bb[j];
        }
#pragma unroll
        for (int i = 0; i < 4; i++)
#pragma unroll
            for (int j = 0; j < 4; j++) {
                float val = sc[i][j] * scale;
                if (kt == qt && (kt * 64 + tx * 4 + j) > (q0 + ty * 4 + i)) val = -1e30f;
                sS[(ty * 4 + i) * 65 + tx * 4 + j] = val;
            }
        __syncthreads();
        // Load V tile (overwrites K; scores already in sS)
        for (int idx = t; idx < 64 * HD_; idx += 256) {
            int r = idx >> 7, d = idx & 127;
            sKV[r * 129 + d] = v[((size_t)(b * S_ + kt * 64 + r) * KV_ + kvh) * HD_ + d];
        }
        // Online softmax: one thread per row
        if (t < 64) {
            float mo = sM[t];
            float mx = mo;
            for (int j = 0; j < 64; j++) mx = fmaxf(mx, sS[t * 65 + j]);
            float al = __expf(mo - mx);
            float sum = 0.0f;
            for (int j = 0; j < 64; j++) {
                float p = __expf(sS[t * 65 + j] - mx);
                sS[t * 65 + j] = p;
                sum += p;
            }
            sM[t] = mx;
            sL[t] = sL[t] * al + sum;
            sAl[t] = al;
        }
        __syncthreads();
        // Rescale + P V  (each thread: rows ty*4.., cols tx*8..)
#pragma unroll
        for (int i = 0; i < 4; i++) {
            float al = sAl[ty * 4 + i];
#pragma unroll
            for (int j = 0; j < 8; j++) acc[i][j] *= al;
        }
        for (int j = 0; j < 64; j++) {
            float p[4], vv[8];
#pragma unroll
            for (int i = 0; i < 4; i++) p[i] = sS[(ty * 4 + i) * 65 + j];
#pragma unroll
            for (int c = 0; c < 8; c++) vv[c] = sKV[j * 129 + tx * 8 + c];
#pragma unroll
            for (int i = 0; i < 4; i++)
#pragma unroll
                for (int c = 0; c < 8; c++) acc[i][c] += p[i] * vv[c];
        }
    }
#pragma unroll
    for (int i = 0; i < 4; i++) {
        float linv = 1.0f / sL[ty * 4 + i];
        float* op = ctx + ((size_t)(b * S_ + q0 + ty * 4 + i) * H_ + h) * HD_ + tx * 8;
#pragma unroll
        for (int j = 0; j < 8; j++) op[j] = acc[i][j] * linv;
    }
}

// ---------------------------------------------------------------------------
extern "C" void kernel_launch(void* const* d_in, const int* in_sizes, int n_in,
                              void* d_out, int out_size) {
    const float* x    = (const float*)d_in[0];
    // d_in[1] = mask (bool) -- causality is hardcoded
    const float* cs   = (const float*)d_in[2];
    const float* sn   = (const float*)d_in[3];
    const float* W_q  = (const float*)d_in[4];
    const float* W_k  = (const float*)d_in[5];
    const float* W_v  = (const float*)d_in[6];
    const float* W_o  = (const float*)d_in[7];
    const float* qnw  = (const float*)d_in[8];
    const float* knw  = (const float*)d_in[9];
    float* out = (float*)d_out;

    float *q, *k, *v, *ctx;
    cudaGetSymbolAddress((void**)&q,   g_q);
    cudaGetSymbolAddress((void**)&k,   g_k);
    cudaGetSymbolAddress((void**)&v,   g_v);
    cudaGetSymbolAddress((void**)&ctx, g_ctx);

    const int M = B_ * S_;  // 4096

    // QKV projections
    {
        dim3 gq(D_ / 128, M / 128);
        sgemm_nt<<<gq, 256>>>(x, W_q, q, M, D_, D_);
        dim3 gk((KV_ * HD_) / 128, M / 128);
        sgemm_nt<<<gk, 256>>>(x, W_k, k, M, KV_ * HD_, D_);
        sgemm_nt<<<gk, 256>>>(x, W_v, v, M, KV_ * HD_, D_);
    }

    // RMSNorm + RoPE
    norm_rope<<<M * H_, 128>>>(q, qnw, cs, sn, H_);
    norm_rope<<<M * KV_, 128>>>(k, knw, cs, sn, KV_);

    // Attention
    {
        static int smem_set = 0;
        const int smem = (64 * 129 * 2 + 64 * 65 + 3 * 64) * sizeof(float);
        if (!smem_set) {
            cudaFuncSetAttribute(flash_attn, cudaFuncAttributeMaxDynamicSharedMemorySize, smem);
            smem_set = 1;
        }
        dim3 g(S_ / 64, H_, B_);
        flash_attn<<<g, 256, smem>>>(q, k, v, ctx);
    }

    // Output projection
    {
        dim3 go(D_ / 128, M / 128);
        sgemm_nt<<<go, 256>>>(ctx, W_o, out, M, D_, D_);
    }
}

// round 6
// speedup vs baseline: 1.5405x; 1.5405x over previous
#include <cuda_runtime.h>
#include <cuda_bf16.h>
#include <math.h>
#include <stdint.h>

#define B_  2
#define S_  2048
#define D_  2048
#define H_  16
#define KV_ 4
#define HD_ 128
#define G_  4

// ---------------- scratch (static device globals; no allocation allowed) ----
__device__ float g_q[(size_t)B_*S_*H_*HD_];    // [B,S,H,HD]
__device__ float g_k[(size_t)B_*S_*KV_*HD_];   // [B,S,KV,HD]
__device__ float g_v[(size_t)B_*S_*KV_*HD_];   // [B,S,KV,HD]
__device__ float g_ctx[(size_t)B_*S_*H_*HD_];  // [B,S,H,HD]

// split-bf16 operands
__device__ __nv_bfloat16 g_x_hi[(size_t)B_*S_*D_],   g_x_lo[(size_t)B_*S_*D_];
__device__ __nv_bfloat16 g_ctx_hi[(size_t)B_*S_*D_], g_ctx_lo[(size_t)B_*S_*D_];
__device__ __nv_bfloat16 g_wq_hi[(size_t)D_*D_],     g_wq_lo[(size_t)D_*D_];
__device__ __nv_bfloat16 g_wo_hi[(size_t)D_*D_],     g_wo_lo[(size_t)D_*D_];
__device__ __nv_bfloat16 g_wk_hi[(size_t)KV_*HD_*D_],g_wk_lo[(size_t)KV_*HD_*D_];
__device__ __nv_bfloat16 g_wv_hi[(size_t)KV_*HD_*D_],g_wv_lo[(size_t)KV_*HD_*D_];

// ---------------- ptx helpers (plain compute_103-safe only) -----------------
__device__ __forceinline__ uint32_t smem_u32(const void* p) {
    uint32_t a;
    asm("{ .reg .u64 t; cvta.to.shared.u64 t, %1; cvt.u32.u64 %0, t; }"
        : "=r"(a) : "l"(p));
    return a;
}
__device__ __forceinline__ void cpa16(uint32_t s, const void* g) {
    asm volatile("cp.async.cg.shared.global [%0], [%1], 16;"
                 :: "r"(s), "l"(g) : "memory");
}
__device__ __forceinline__ void cpa_commit() {
    asm volatile("cp.async.commit_group;" ::: "memory");
}
template<int N> __device__ __forceinline__ void cpa_wait() {
    asm volatile("cp.async.wait_group %0;" :: "n"(N) : "memory");
}
__device__ __forceinline__ void ldsm4(uint32_t* r, uint32_t addr) {
    asm volatile("ldmatrix.sync.aligned.m8n8.x4.shared.b16 {%0,%1,%2,%3}, [%4];"
                 : "=r"(r[0]), "=r"(r[1]), "=r"(r[2]), "=r"(r[3]) : "r"(addr));
}
__device__ __forceinline__ void mma16816(float* c, const uint32_t* a, const uint32_t* b) {
    asm volatile(
        "mma.sync.aligned.m16n8k16.row.col.f32.bf16.bf16.f32 "
        "{%0,%1,%2,%3}, {%4,%5,%6,%7}, {%8,%9}, {%0,%1,%2,%3};"
        : "+f"(c[0]), "+f"(c[1]), "+f"(c[2]), "+f"(c[3])
        : "r"(a[0]), "r"(a[1]), "r"(a[2]), "r"(a[3]), "r"(b[0]), "r"(b[1]));
}

// ---------------------------------------------------------------------------
// split fp32 -> (hi, lo) bf16
// ---------------------------------------------------------------------------
__global__ __launch_bounds__(256) void split_bf16(const float* __restrict__ s,
                                                  __nv_bfloat16* __restrict__ hi,
                                                  __nv_bfloat16* __restrict__ lo,
                                                  int n4) {
    int i = blockIdx.x * 256 + threadIdx.x;
    if (i >= n4) return;
    float4 v = ((const float4*)s)[i];
    __nv_bfloat16 h0 = __float2bfloat16(v.x), h1 = __float2bfloat16(v.y);
    __nv_bfloat16 h2 = __float2bfloat16(v.z), h3 = __float2bfloat16(v.w);
    __nv_bfloat16 l0 = __float2bfloat16(v.x - __bfloat162float(h0));
    __nv_bfloat16 l1 = __float2bfloat16(v.y - __bfloat162float(h1));
    __nv_bfloat16 l2 = __float2bfloat16(v.z - __bfloat162float(h2));
    __nv_bfloat16 l3 = __float2bfloat16(v.w - __bfloat162float(h3));
    __nv_bfloat162* hp = (__nv_bfloat162*)(hi + (size_t)i * 4);
    __nv_bfloat162* lp = (__nv_bfloat162*)(lo + (size_t)i * 4);
    hp[0] = __nv_bfloat162(h0, h1); hp[1] = __nv_bfloat162(h2, h3);
    lp[0] = __nv_bfloat162(l0, l1); lp[1] = __nv_bfloat162(l2, l3);
}

// ---------------------------------------------------------------------------
// mma.sync split-bf16 GEMM: C[M,N] = (Ahi+Alo)[M,K] * (Bhi+Blo)[N,K]^T
// 128x128 tile, BK=32, 3-stage cp.async pipeline, 8 warps (2m x 4n),
// warp tile 64x32 = 4x4 m16n8k16 frags, 3 MMA terms (hh, hl, lh), fp32 acc.
// smem rows padded to 40 bf16 (80 B) -> conflict-free ldmatrix.
// ---------------------------------------------------------------------------
#define BKC 32
#define ROWPAD 40                          // bf16 elems per row (32 + 8 pad)
#define TILEB (128 * ROWPAD * 2)           // 10240 B per tile
#define STAGEB (4 * TILEB)                 // Ahi | Alo | Bhi | Blo
#define STAGES 3
#define GT_SMEM (STAGES * STAGEB)          // 122880 B

__global__ __launch_bounds__(256, 1) void gemm_mma(
    const __nv_bfloat16* __restrict__ Ahi, const __nv_bfloat16* __restrict__ Alo,
    const __nv_bfloat16* __restrict__ Bhi, const __nv_bfloat16* __restrict__ Blo,
    float* __restrict__ C, int M, int N, int K)
{
    extern __shared__ char sm[];
    const uint32_t sb = smem_u32(sm);
    const int tid = threadIdx.x;
    const int wid = tid >> 5, lane = tid & 31;
    const int wm = (wid >> 2) * 64;         // warp m offset in tile
    const int wn = (wid & 3) * 32;          // warp n offset in tile
    const int rowBase = blockIdx.y * 128;
    const int colBase = blockIdx.x * 128;
    const int NC = K / BKC;

    const __nv_bfloat16* srcs[4] = {
        Ahi + (size_t)rowBase * K, Alo + (size_t)rowBase * K,
        Bhi + (size_t)colBase * K, Blo + (size_t)colBase * K };

    // ---- async loader: one chunk = 4 tiles of 128x32 bf16 -------------------
    auto load_chunk = [&](int c) {
        uint32_t stb = sb + (uint32_t)(c % STAGES) * STAGEB;
#pragma unroll
        for (int j = 0; j < 8; j++) {
            int idx = tid + j * 256;        // 0..2047
            int t4 = idx >> 9;              // tile 0..3
            int e  = idx & 511;             // entry in tile
            int r  = e >> 2, c4 = e & 3;    // row 0..127, 16B-chunk 0..3
            uint32_t dst = stb + (uint32_t)t4 * TILEB + (uint32_t)(r * 80 + c4 * 16);
            cpa16(dst, srcs[t4] + (size_t)c * BKC + (size_t)r * K + c4 * 8);
        }
        cpa_commit();
    };

    // lane-invariant ldmatrix sub-offsets (bytes)
    const uint32_t aoff = (uint32_t)((lane & 15) * 80 + (lane >> 4) * 16);
    const uint32_t boff = (uint32_t)(((lane & 7) + 8 * (lane >> 4)) * 80 +
                                     ((lane >> 3) & 1) * 16);

    float acc[4][4][4];
#pragma unroll
    for (int mi = 0; mi < 4; mi++)
#pragma unroll
        for (int nj = 0; nj < 4; nj++)
#pragma unroll
            for (int e = 0; e < 4; e++) acc[mi][nj][e] = 0.0f;

    load_chunk(0);
    load_chunk(1);
    load_chunk(2);

    for (int c = 0; c < NC; c++) {
        cpa_wait<2>();
        __syncthreads();

        uint32_t stb = sb + (uint32_t)(c % STAGES) * STAGEB;
        const uint32_t sAhi = stb, sAlo = stb + TILEB;
        const uint32_t sBhi = stb + 2 * TILEB, sBlo = stb + 3 * TILEB;

#pragma unroll
        for (int ks = 0; ks < 2; ks++) {
            uint32_t kb = (uint32_t)(32 * ks);
            uint32_t bhi[4][2], blo[4][2];
#pragma unroll
            for (int njp = 0; njp < 2; njp++) {
                uint32_t r4[4];
                uint32_t bo = (uint32_t)((wn + 16 * njp) * 80) + kb + boff;
                ldsm4(r4, sBhi + bo);
                bhi[2 * njp][0] = r4[0]; bhi[2 * njp][1] = r4[1];
                bhi[2 * njp + 1][0] = r4[2]; bhi[2 * njp + 1][1] = r4[3];
                ldsm4(r4, sBlo + bo);
                blo[2 * njp][0] = r4[0]; blo[2 * njp][1] = r4[1];
                blo[2 * njp + 1][0] = r4[2]; blo[2 * njp + 1][1] = r4[3];
            }
#pragma unroll
            for (int mi = 0; mi < 4; mi++) {
                uint32_t ahi[4], alo[4];
                uint32_t ao = (uint32_t)((wm + 16 * mi) * 80) + kb + aoff;
                ldsm4(ahi, sAhi + ao);
                ldsm4(alo, sAlo + ao);
#pragma unroll
                for (int nj = 0; nj < 4; nj++) {
                    mma16816(acc[mi][nj], ahi, bhi[nj]);
                    mma16816(acc[mi][nj], ahi, blo[nj]);
                    mma16816(acc[mi][nj], alo, bhi[nj]);
                }
            }
        }
        __syncthreads();
        if (c + 3 < NC) load_chunk(c + 3);
        else cpa_commit();   // keep group count aligned with wait<2>
    }

    // ---- epilogue: fragment -> C (fp32) ------------------------------------
    const int r0 = rowBase + wm + (lane >> 2);
    const int c0 = colBase + wn + 2 * (lane & 3);
#pragma unroll
    for (int mi = 0; mi < 4; mi++) {
#pragma unroll
        for (int nj = 0; nj < 4; nj++) {
            float* p0 = C + (size_t)(r0 + 16 * mi) * N + c0 + 8 * nj;
            float* p1 = p0 + (size_t)8 * N;
            *(float2*)p0 = make_float2(acc[mi][nj][0], acc[mi][nj][1]);
            *(float2*)p1 = make_float2(acc[mi][nj][2], acc[mi][nj][3]);
        }
    }
}

// ---------------------------------------------------------------------------
// Fused RMSNorm + RoPE, in place. One block (128 thr) per (b,s,head) row.
// ---------------------------------------------------------------------------
__global__ __launch_bounds__(128) void norm_rope(float* __restrict__ t,
                                                 const float* __restrict__ w,
                                                 const float* __restrict__ cs,
                                                 const float* __restrict__ sn,
                                                 int nh) {
    const int row = blockIdx.x;
    const int s = (row / nh) % S_;
    const int i = threadIdx.x;
    float* p = t + (size_t)row * HD_;
    float v = p[i];
    float ss = v * v;
#pragma unroll
    for (int o = 16; o; o >>= 1) ss += __shfl_xor_sync(0xffffffff, ss, o);
    __shared__ float wsum[4];
    __shared__ float nbuf[HD_];
    if ((i & 31) == 0) wsum[i >> 5] = ss;
    __syncthreads();
    float tot = wsum[0] + wsum[1] + wsum[2] + wsum[3];
    float rstd = rsqrtf(tot * (1.0f / HD_) + 1e-5f);
    float n = v * rstd * w[i];
    nbuf[i] = n;
    __syncthreads();
    float rot = (i < 64) ? -nbuf[i + 64] : nbuf[i - 64];
    p[i] = n * cs[s * HD_ + i] + rot * sn[s * HD_ + i];
}

// ---------------------------------------------------------------------------
// Causal GQA flash attention, fp32. BQ=BK=64, HD=128, 256 threads.
// ---------------------------------------------------------------------------
__global__ __launch_bounds__(256) void flash_attn(const float* __restrict__ q,
                                                  const float* __restrict__ k,
                                                  const float* __restrict__ v,
                                                  float* __restrict__ ctx) {
    extern __shared__ float smf[];
    float* sQ  = smf;
    float* sKV = sQ + 64 * 129;
    float* sS  = sKV + 64 * 129;
    float* sM  = sS + 64 * 65;
    float* sL  = sM + 64;
    float* sAl = sL + 64;

    const int b = blockIdx.z, h = blockIdx.y, qt = blockIdx.x;
    const int kvh = h / G_;
    const int q0 = qt * 64;
    const int t = threadIdx.x;
    const int ty = t >> 4, tx = t & 15;
    const float scale = 0.08838834764831845f;

    for (int idx = t; idx < 64 * HD_; idx += 256) {
        int r = idx >> 7, d = idx & 127;
        sQ[r * 129 + d] = q[((size_t)(b * S_ + q0 + r) * H_ + h) * HD_ + d];
    }
    if (t < 64) { sM[t] = -1e30f; sL[t] = 0.0f; }

    float acc[4][8];
#pragma unroll
    for (int i = 0; i < 4; i++)
#pragma unroll
        for (int j = 0; j < 8; j++) acc[i][j] = 0.0f;

    for (int kt = 0; kt <= qt; kt++) {
        __syncthreads();
        for (int idx = t; idx < 64 * HD_; idx += 256) {
            int r = idx >> 7, d = idx & 127;
            sKV[r * 129 + d] = k[((size_t)(b * S_ + kt * 64 + r) * KV_ + kvh) * HD_ + d];
        }
        __syncthreads();
        float sc[4][4];
#pragma unroll
        for (int i = 0; i < 4; i++)
#pragma unroll
            for (int j = 0; j < 4; j++) sc[i][j] = 0.0f;
        for (int d = 0; d < HD_; d++) {
            float a[4], bb[4];
#pragma unroll
            for (int i = 0; i < 4; i++) a[i] = sQ[(ty * 4 + i) * 129 + d];
#pragma unroll
            for (int j = 0; j < 4; j++) bb[j] = sKV[(tx * 4 + j) * 129 + d];
#pragma unroll
            for (int i = 0; i < 4; i++)
#pragma unroll
                for (int j = 0; j < 4; j++) sc[i][j] += a[i] * bb[j];
        }
#pragma unroll
        for (int i = 0; i < 4; i++)
#pragma unroll
            for (int j = 0; j < 4; j++) {
                float val = sc[i][j] * scale;
                if (kt == qt && (kt * 64 + tx * 4 + j) > (q0 + ty * 4 + i)) val = -1e30f;
                sS[(ty * 4 + i) * 65 + tx * 4 + j] = val;
            }
        __syncthreads();
        for (int idx = t; idx < 64 * HD_; idx += 256) {
            int r = idx >> 7, d = idx & 127;
            sKV[r * 129 + d] = v[((size_t)(b * S_ + kt * 64 + r) * KV_ + kvh) * HD_ + d];
        }
        if (t < 64) {
            float mo = sM[t];
            float mx = mo;
            for (int j = 0; j < 64; j++) mx = fmaxf(mx, sS[t * 65 + j]);
            float al = __expf(mo - mx);
            float sum = 0.0f;
            for (int j = 0; j < 64; j++) {
                float p = __expf(sS[t * 65 + j] - mx);
                sS[t * 65 + j] = p;
                sum += p;
            }
            sM[t] = mx;
            sL[t] = sL[t] * al + sum;
            sAl[t] = al;
        }
        __syncthreads();
#pragma unroll
        for (int i = 0; i < 4; i++) {
            float al = sAl[ty * 4 + i];
#pragma unroll
            for (int j = 0; j < 8; j++) acc[i][j] *= al;
        }
        for (int j = 0; j < 64; j++) {
            float p[4], vv[8];
#pragma unroll
            for (int i = 0; i < 4; i++) p[i] = sS[(ty * 4 + i) * 65 + j];
#pragma unroll
            for (int c = 0; c < 8; c++) vv[c] = sKV[j * 129 + tx * 8 + c];
#pragma unroll
            for (int i = 0; i < 4; i++)
#pragma unroll
                for (int c = 0; c < 8; c++) acc[i][c] += p[i] * vv[c];
        }
    }
#pragma unroll
    for (int i = 0; i < 4; i++) {
        float linv = 1.0f / sL[ty * 4 + i];
        float* op = ctx + ((size_t)(b * S_ + q0 + ty * 4 + i) * H_ + h) * HD_ + tx * 8;
#pragma unroll
        for (int j = 0; j < 8; j++) op[j] = acc[i][j] * linv;
    }
}

// ---------------------------------------------------------------------------
extern "C" void kernel_launch(void* const* d_in, const int* in_sizes, int n_in,
                              void* d_out, int out_size) {
    const float* x    = (const float*)d_in[0];
    const float* cs   = (const float*)d_in[2];
    const float* sn   = (const float*)d_in[3];
    const float* W_q  = (const float*)d_in[4];
    const float* W_k  = (const float*)d_in[5];
    const float* W_v  = (const float*)d_in[6];
    const float* W_o  = (const float*)d_in[7];
    const float* qnw  = (const float*)d_in[8];
    const float* knw  = (const float*)d_in[9];
    float* out = (float*)d_out;

    float *q, *k, *v, *ctx;
    cudaGetSymbolAddress((void**)&q,   g_q);
    cudaGetSymbolAddress((void**)&k,   g_k);
    cudaGetSymbolAddress((void**)&v,   g_v);
    cudaGetSymbolAddress((void**)&ctx, g_ctx);
    __nv_bfloat16 *xh, *xl, *ch, *cl, *wqh, *wql, *wkh, *wkl, *wvh, *wvl, *woh, *wol;
    cudaGetSymbolAddress((void**)&xh,  g_x_hi);   cudaGetSymbolAddress((void**)&xl,  g_x_lo);
    cudaGetSymbolAddress((void**)&ch,  g_ctx_hi); cudaGetSymbolAddress((void**)&cl,  g_ctx_lo);
    cudaGetSymbolAddress((void**)&wqh, g_wq_hi);  cudaGetSymbolAddress((void**)&wql, g_wq_lo);
    cudaGetSymbolAddress((void**)&wkh, g_wk_hi);  cudaGetSymbolAddress((void**)&wkl, g_wk_lo);
    cudaGetSymbolAddress((void**)&wvh, g_wv_hi);  cudaGetSymbolAddress((void**)&wvl, g_wv_lo);
    cudaGetSymbolAddress((void**)&woh, g_wo_hi);  cudaGetSymbolAddress((void**)&wol, g_wo_lo);

    static int attr_set = 0;
    if (!attr_set) {
        cudaFuncSetAttribute(gemm_mma, cudaFuncAttributeMaxDynamicSharedMemorySize, GT_SMEM);
        const int fsmem = (64 * 129 * 2 + 64 * 65 + 3 * 64) * sizeof(float);
        cudaFuncSetAttribute(flash_attn, cudaFuncAttributeMaxDynamicSharedMemorySize, fsmem);
        attr_set = 1;
    }

    const int M = B_ * S_;          // 4096
    const int NXY = M * D_ / 4;
    const int NW  = D_ * D_ / 4;
    const int NKV = KV_ * HD_ * D_ / 4;

    // split inputs to (hi, lo) bf16
    split_bf16<<<(NXY + 255) / 256, 256>>>(x,   xh,  xl,  NXY);
    split_bf16<<<(NW  + 255) / 256, 256>>>(W_q, wqh, wql, NW);
    split_bf16<<<(NKV + 255) / 256, 256>>>(W_k, wkh, wkl, NKV);
    split_bf16<<<(NKV + 255) / 256, 256>>>(W_v, wvh, wvl, NKV);
    split_bf16<<<(NW  + 255) / 256, 256>>>(W_o, woh, wol, NW);

    // QKV projections (tensor core, mma.sync)
    {
        dim3 gq(D_ / 128, M / 128);
        gemm_mma<<<gq, 256, GT_SMEM>>>(xh, xl, wqh, wql, q, M, D_, D_);
        dim3 gk((KV_ * HD_) / 128, M / 128);
        gemm_mma<<<gk, 256, GT_SMEM>>>(xh, xl, wkh, wkl, k, M, KV_ * HD_, D_);
        gemm_mma<<<gk, 256, GT_SMEM>>>(xh, xl, wvh, wvl, v, M, KV_ * HD_, D_);
    }

    // RMSNorm + RoPE
    norm_rope<<<M * H_, 128>>>(q, qnw, cs, sn, H_);
    norm_rope<<<M * KV_, 128>>>(k, knw, cs, sn, KV_);

    // Attention (fp32 SIMT)
    {
        const int fsmem = (64 * 129 * 2 + 64 * 65 + 3 * 64) * sizeof(float);
        dim3 g(S_ / 64, H_, B_);
        flash_attn<<<g, 256, fsmem>>>(q, k, v, ctx);
    }

    // Output projection (tensor core, mma.sync)
    split_bf16<<<(NXY + 255) / 256, 256>>>(ctx, ch, cl, NXY);
    {
        dim3 go(D_ / 128, M / 128);
        gemm_mma<<<go, 256, GT_SMEM>>>(ch, cl, woh, wol, out, M, D_, D_);
    }
}

// round 9
// speedup vs baseline: 3.5589x; 2.3102x over previous
#include <cuda_runtime.h>
#include <cuda_bf16.h>
#include <math.h>
#include <stdint.h>

#define B_  2
#define S_  2048
#define D_  2048
#define H_  16
#define KV_ 4
#define HD_ 128
#define G_  4

// ---------------- scratch (static device globals; no allocation allowed) ----
__device__ float g_q[(size_t)B_*S_*H_*HD_];    // [B,S,H,HD]
__device__ float g_k[(size_t)B_*S_*KV_*HD_];   // [B,S,KV,HD]
__device__ float g_v[(size_t)B_*S_*KV_*HD_];   // [B,S,KV,HD]
__device__ float g_ctx[(size_t)B_*S_*H_*HD_];  // [B,S,H,HD]

// split-bf16 operands
__device__ __nv_bfloat16 g_x_hi[(size_t)B_*S_*D_],   g_x_lo[(size_t)B_*S_*D_];
__device__ __nv_bfloat16 g_ctx_hi[(size_t)B_*S_*D_], g_ctx_lo[(size_t)B_*S_*D_];
__device__ __nv_bfloat16 g_wq_hi[(size_t)D_*D_],     g_wq_lo[(size_t)D_*D_];
__device__ __nv_bfloat16 g_wo_hi[(size_t)D_*D_],     g_wo_lo[(size_t)D_*D_];
__device__ __nv_bfloat16 g_wk_hi[(size_t)KV_*HD_*D_],g_wk_lo[(size_t)KV_*HD_*D_];
__device__ __nv_bfloat16 g_wv_hi[(size_t)KV_*HD_*D_],g_wv_lo[(size_t)KV_*HD_*D_];
// attention hi/lo buffers
__device__ __nv_bfloat16 g_qhi[(size_t)B_*S_*H_*HD_],  g_qlo[(size_t)B_*S_*H_*HD_];
__device__ __nv_bfloat16 g_khi[(size_t)B_*S_*KV_*HD_], g_klo[(size_t)B_*S_*KV_*HD_];
__device__ __nv_bfloat16 g_vhi[(size_t)B_*S_*KV_*HD_], g_vlo[(size_t)B_*S_*KV_*HD_];

// ---------------- ptx helpers (plain compute_103-safe only) -----------------
__device__ __forceinline__ uint32_t smem_u32(const void* p) {
    uint32_t a;
    asm("{ .reg .u64 t; cvta.to.shared.u64 t, %1; cvt.u32.u64 %0, t; }"
        : "=r"(a) : "l"(p));
    return a;
}
__device__ __forceinline__ void cpa16(uint32_t s, const void* g) {
    asm volatile("cp.async.cg.shared.global [%0], [%1], 16;"
                 :: "r"(s), "l"(g) : "memory");
}
__device__ __forceinline__ void cpa_commit() {
    asm volatile("cp.async.commit_group;" ::: "memory");
}
template<int N> __device__ __forceinline__ void cpa_wait() {
    asm volatile("cp.async.wait_group %0;" :: "n"(N) : "memory");
}
__device__ __forceinline__ void ldsm4(uint32_t* r, uint32_t addr) {
    asm volatile("ldmatrix.sync.aligned.m8n8.x4.shared.b16 {%0,%1,%2,%3}, [%4];"
                 : "=r"(r[0]), "=r"(r[1]), "=r"(r[2]), "=r"(r[3]) : "r"(addr));
}
__device__ __forceinline__ void ldsm4t(uint32_t* r, uint32_t addr) {
    asm volatile("ldmatrix.sync.aligned.m8n8.x4.trans.shared.b16 {%0,%1,%2,%3}, [%4];"
                 : "=r"(r[0]), "=r"(r[1]), "=r"(r[2]), "=r"(r[3]) : "r"(addr));
}
__device__ __forceinline__ void mma16816(float* c, const uint32_t* a, const uint32_t* b) {
    asm volatile(
        "mma.sync.aligned.m16n8k16.row.col.f32.bf16.bf16.f32 "
        "{%0,%1,%2,%3}, {%4,%5,%6,%7}, {%8,%9}, {%0,%1,%2,%3};"
        : "+f"(c[0]), "+f"(c[1]), "+f"(c[2]), "+f"(c[3])
        : "r"(a[0]), "r"(a[1]), "r"(a[2]), "r"(a[3]), "r"(b[0]), "r"(b[1]));
}
__device__ __forceinline__ void split2(float a, float b, uint32_t& hi, uint32_t& lo) {
    __nv_bfloat162 h = __floats2bfloat162_rn(a, b);
    hi = *(uint32_t*)&h;
    float ra = a - __bfloat162float(h.x);
    float rb = b - __bfloat162float(h.y);
    __nv_bfloat162 l = __floats2bfloat162_rn(ra, rb);
    lo = *(uint32_t*)&l;
}

// ---------------------------------------------------------------------------
// split fp32 -> (hi, lo) bf16
// ---------------------------------------------------------------------------
__global__ __launch_bounds__(256) void split_bf16(const float* __restrict__ s,
                                                  __nv_bfloat16* __restrict__ hi,
                                                  __nv_bfloat16* __restrict__ lo,
                                                  int n4) {
    int i = blockIdx.x * 256 + threadIdx.x;
    if (i >= n4) return;
    float4 v = ((const float4*)s)[i];
    __nv_bfloat16 h0 = __float2bfloat16(v.x), h1 = __float2bfloat16(v.y);
    __nv_bfloat16 h2 = __float2bfloat16(v.z), h3 = __float2bfloat16(v.w);
    __nv_bfloat16 l0 = __float2bfloat16(v.x - __bfloat162float(h0));
    __nv_bfloat16 l1 = __float2bfloat16(v.y - __bfloat162float(h1));
    __nv_bfloat16 l2 = __float2bfloat16(v.z - __bfloat162float(h2));
    __nv_bfloat16 l3 = __float2bfloat16(v.w - __bfloat162float(h3));
    __nv_bfloat162* hp = (__nv_bfloat162*)(hi + (size_t)i * 4);
    __nv_bfloat162* lp = (__nv_bfloat162*)(lo + (size_t)i * 4);
    hp[0] = __nv_bfloat162(h0, h1); hp[1] = __nv_bfloat162(h2, h3);
    lp[0] = __nv_bfloat162(l0, l1); lp[1] = __nv_bfloat162(l2, l3);
}

// ---------------------------------------------------------------------------
// mma.sync split-bf16 GEMM (unchanged from R5)
// ---------------------------------------------------------------------------
#define BKC 32
#define TILEB (128 * 40 * 2)
#define STAGEB (4 * TILEB)
#define STAGES 3
#define GT_SMEM (STAGES * STAGEB)

__global__ __launch_bounds__(256, 1) void gemm_mma(
    const __nv_bfloat16* __restrict__ Ahi, const __nv_bfloat16* __restrict__ Alo,
    const __nv_bfloat16* __restrict__ Bhi, const __nv_bfloat16* __restrict__ Blo,
    float* __restrict__ C, int M, int N, int K)
{
    extern __shared__ char sm[];
    const uint32_t sb = smem_u32(sm);
    const int tid = threadIdx.x;
    const int wid = tid >> 5, lane = tid & 31;
    const int wm = (wid >> 2) * 64;
    const int wn = (wid & 3) * 32;
    const int rowBase = blockIdx.y * 128;
    const int colBase = blockIdx.x * 128;
    const int NC = K / BKC;

    const __nv_bfloat16* srcs[4] = {
        Ahi + (size_t)rowBase * K, Alo + (size_t)rowBase * K,
        Bhi + (size_t)colBase * K, Blo + (size_t)colBase * K };

    auto load_chunk = [&](int c) {
        uint32_t stb = sb + (uint32_t)(c % STAGES) * STAGEB;
#pragma unroll
        for (int j = 0; j < 8; j++) {
            int idx = tid + j * 256;
            int t4 = idx >> 9;
            int e  = idx & 511;
            int r  = e >> 2, c4 = e & 3;
            uint32_t dst = stb + (uint32_t)t4 * TILEB + (uint32_t)(r * 80 + c4 * 16);
            cpa16(dst, srcs[t4] + (size_t)c * BKC + (size_t)r * K + c4 * 8);
        }
        cpa_commit();
    };

    const uint32_t aoff = (uint32_t)((lane & 15) * 80 + (lane >> 4) * 16);
    const uint32_t boff = (uint32_t)(((lane & 7) + 8 * (lane >> 4)) * 80 +
                                     ((lane >> 3) & 1) * 16);

    float acc[4][4][4];
#pragma unroll
    for (int mi = 0; mi < 4; mi++)
#pragma unroll
        for (int nj = 0; nj < 4; nj++)
#pragma unroll
            for (int e = 0; e < 4; e++) acc[mi][nj][e] = 0.0f;

    load_chunk(0);
    load_chunk(1);
    load_chunk(2);

    for (int c = 0; c < NC; c++) {
        cpa_wait<2>();
        __syncthreads();

        uint32_t stb = sb + (uint32_t)(c % STAGES) * STAGEB;
        const uint32_t sAhi = stb, sAlo = stb + TILEB;
        const uint32_t sBhi = stb + 2 * TILEB, sBlo = stb + 3 * TILEB;

#pragma unroll
        for (int ks = 0; ks < 2; ks++) {
            uint32_t kb = (uint32_t)(32 * ks);
            uint32_t bhi[4][2], blo[4][2];
#pragma unroll
            for (int njp = 0; njp < 2; njp++) {
                uint32_t r4[4];
                uint32_t bo = (uint32_t)((wn + 16 * njp) * 80) + kb + boff;
                ldsm4(r4, sBhi + bo);
                bhi[2 * njp][0] = r4[0]; bhi[2 * njp][1] = r4[1];
                bhi[2 * njp + 1][0] = r4[2]; bhi[2 * njp + 1][1] = r4[3];
                ldsm4(r4, sBlo + bo);
                blo[2 * njp][0] = r4[0]; blo[2 * njp][1] = r4[1];
                blo[2 * njp + 1][0] = r4[2]; blo[2 * njp + 1][1] = r4[3];
            }
#pragma unroll
            for (int mi = 0; mi < 4; mi++) {
                uint32_t ahi[4], alo[4];
                uint32_t ao = (uint32_t)((wm + 16 * mi) * 80) + kb + aoff;
                ldsm4(ahi, sAhi + ao);
                ldsm4(alo, sAlo + ao);
#pragma unroll
                for (int nj = 0; nj < 4; nj++) {
                    mma16816(acc[mi][nj], ahi, bhi[nj]);
                    mma16816(acc[mi][nj], ahi, blo[nj]);
                    mma16816(acc[mi][nj], alo, bhi[nj]);
                }
            }
        }
        __syncthreads();
        if (c + 3 < NC) load_chunk(c + 3);
        else cpa_commit();
    }

    const int r0 = rowBase + wm + (lane >> 2);
    const int c0 = colBase + wn + 2 * (lane & 3);
#pragma unroll
    for (int mi = 0; mi < 4; mi++) {
#pragma unroll
        for (int nj = 0; nj < 4; nj++) {
            float* p0 = C + (size_t)(r0 + 16 * mi) * N + c0 + 8 * nj;
            float* p1 = p0 + (size_t)8 * N;
            *(float2*)p0 = make_float2(acc[mi][nj][0], acc[mi][nj][1]);
            *(float2*)p1 = make_float2(acc[mi][nj][2], acc[mi][nj][3]);
        }
    }
}

// ---------------------------------------------------------------------------
// Fused RMSNorm + RoPE, in place.
// ---------------------------------------------------------------------------
__global__ __launch_bounds__(128) void norm_rope(float* __restrict__ t,
                                                 const float* __restrict__ w,
                                                 const float* __restrict__ cs,
                                                 const float* __restrict__ sn,
                                                 int nh) {
    const int row = blockIdx.x;
    const int s = (row / nh) % S_;
    const int i = threadIdx.x;
    float* p = t + (size_t)row * HD_;
    float v = p[i];
    float ss = v * v;
#pragma unroll
    for (int o = 16; o; o >>= 1) ss += __shfl_xor_sync(0xffffffff, ss, o);
    __shared__ float wsum[4];
    __shared__ float nbuf[HD_];
    if ((i & 31) == 0) wsum[i >> 5] = ss;
    __syncthreads();
    float tot = wsum[0] + wsum[1] + wsum[2] + wsum[3];
    float rstd = rsqrtf(tot * (1.0f / HD_) + 1e-5f);
    float n = v * rstd * w[i];
    nbuf[i] = n;
    __syncthreads();
    float rot = (i < 64) ? -nbuf[i + 64] : nbuf[i - 64];
    p[i] = n * cs[s * HD_ + i] + rot * sn[s * HD_ + i];
}

// ---------------------------------------------------------------------------
// mma.sync split-bf16 causal GQA flash attention.
// BQ=128, BKV=64, HD=128. 8 warps x 16 q-rows. Double-buffered K/V.
// ---------------------------------------------------------------------------
#define FA_ROWB 272                 // 136 bf16 elems per row (128 + 8 pad)
#define FA_QT  (128 * FA_ROWB)      // 34816 B per Q tile
#define FA_KVT (64 * FA_ROWB)       // 17408 B per KV tile
#define FA_STAGE (4 * FA_KVT)       // Kh | Kl | Vh | Vl
#define FA_SMEM (2 * FA_QT + 2 * FA_STAGE)   // 208896 B

__global__ __launch_bounds__(256, 1) void flash_mma(
    const __nv_bfloat16* __restrict__ qh, const __nv_bfloat16* __restrict__ ql,
    const __nv_bfloat16* __restrict__ kh, const __nv_bfloat16* __restrict__ kl,
    const __nv_bfloat16* __restrict__ vh, const __nv_bfloat16* __restrict__ vl,
    float* __restrict__ ctx)
{
    extern __shared__ char sm[];
    const uint32_t sb  = smem_u32(sm);
    const uint32_t sQh = sb, sQl = sb + FA_QT;
    const uint32_t sKV0 = sb + 2 * FA_QT;

    const int b = blockIdx.z, head = blockIdx.y;
    const int qt = gridDim.x - 1 - blockIdx.x;     // big tiles first
    const int q0 = qt * 128;
    const int kvh = head / G_;
    const int tid = threadIdx.x, wid = tid >> 5, lane = tid & 31;
    const int m0 = wid * 16;
    const float scale = 0.08838834764831845f;

    // ---- Q tile (hi/lo) via cp.async ----
    {
        const __nv_bfloat16* srcs[2] = { qh, ql };
#pragma unroll
        for (int j = 0; j < 16; j++) {
            int idx = tid + j * 256;
            int t = idx >> 11;
            int e = idx & 2047;
            int r = e >> 4, c = e & 15;
            uint32_t dst = (t ? sQl : sQh) + (uint32_t)(r * FA_ROWB + c * 16);
            cpa16(dst, srcs[t] + ((size_t)(b * S_ + q0 + r) * H_ + head) * HD_ + c * 8);
        }
    }
    auto load_kv = [&](int kt) {
        uint32_t st = sKV0 + (uint32_t)(kt & 1) * FA_STAGE;
        const __nv_bfloat16* srcs[4] = { kh, kl, vh, vl };
#pragma unroll
        for (int j = 0; j < 16; j++) {
            int idx = tid + j * 256;
            int t4 = idx >> 10;
            int e = idx & 1023;
            int r = e >> 4, c = e & 15;
            uint32_t dst = st + (uint32_t)t4 * FA_KVT + (uint32_t)(r * FA_ROWB + c * 16);
            cpa16(dst, srcs[t4] + ((size_t)(b * S_ + kt * 64 + r) * KV_ + kvh) * HD_ + c * 8);
        }
    };
    load_kv(0);
    cpa_commit();                    // group: Q + stage0

    const uint32_t aoff = (uint32_t)((lane & 15) * FA_ROWB + (lane >> 4) * 16);
    const uint32_t boff = (uint32_t)(((lane & 7) + 8 * (lane >> 4)) * FA_ROWB +
                                     ((lane >> 3) & 1) * 16);

    float oacc[16][4];
#pragma unroll
    for (int nf = 0; nf < 16; nf++)
#pragma unroll
        for (int e = 0; e < 4; e++) oacc[nf][e] = 0.0f;
    float mold[2] = { -1e30f, -1e30f }, lsum[2] = { 0.0f, 0.0f };

    const int nkv = 2 * (qt + 1);
    for (int kt = 0; kt < nkv; kt++) {
        if (kt + 1 < nkv) { load_kv(kt + 1); cpa_commit(); cpa_wait<1>(); }
        else cpa_wait<0>();
        __syncthreads();

        uint32_t st = sKV0 + (uint32_t)(kt & 1) * FA_STAGE;
        uint32_t sKh = st, sKl = st + FA_KVT;
        uint32_t sVh = st + 2 * FA_KVT, sVl = st + 3 * FA_KVT;

        // ---- S = Q K^T (3 terms) ----
        float sacc[8][4];
#pragma unroll
        for (int nf = 0; nf < 8; nf++)
#pragma unroll
            for (int e = 0; e < 4; e++) sacc[nf][e] = 0.0f;
#pragma unroll
        for (int ks = 0; ks < 8; ks++) {
            uint32_t bh[8][2], bl[8][2];
#pragma unroll
            for (int njp = 0; njp < 4; njp++) {
                uint32_t r4[4];
                uint32_t bo = (uint32_t)(16 * njp * FA_ROWB) + ks * 32 + boff;
                ldsm4(r4, sKh + bo);
                bh[2 * njp][0] = r4[0]; bh[2 * njp][1] = r4[1];
                bh[2 * njp + 1][0] = r4[2]; bh[2 * njp + 1][1] = r4[3];
                ldsm4(r4, sKl + bo);
                bl[2 * njp][0] = r4[0]; bl[2 * njp][1] = r4[1];
                bl[2 * njp + 1][0] = r4[2]; bl[2 * njp + 1][1] = r4[3];
            }
            uint32_t ah[4], al[4];
            uint32_t ao = (uint32_t)(m0 * FA_ROWB) + ks * 32 + aoff;
            ldsm4(ah, sQh + ao);
            ldsm4(al, sQl + ao);
#pragma unroll
            for (int nf = 0; nf < 8; nf++) {
                mma16816(sacc[nf], ah, bh[nf]);
                mma16816(sacc[nf], ah, bl[nf]);
                mma16816(sacc[nf], al, bh[nf]);
            }
        }

        // ---- online softmax (rows: lane>>2 and +8) ----
        const bool diag = (kt >= 2 * qt);
        float alpha[2];
#pragma unroll
        for (int hh = 0; hh < 2; hh++) {
            int rowg = q0 + m0 + (lane >> 2) + 8 * hh;
            float mx = mold[hh];
#pragma unroll
            for (int nf = 0; nf < 8; nf++)
#pragma unroll
                for (int e = 0; e < 2; e++) {
                    float v = sacc[nf][2 * hh + e] * scale;
                    if (diag) {
                        int colg = kt * 64 + nf * 8 + 2 * (lane & 3) + e;
                        if (colg > rowg) v = -1e30f;
                    }
                    sacc[nf][2 * hh + e] = v;
                    mx = fmaxf(mx, v);
                }
            mx = fmaxf(mx, __shfl_xor_sync(0xffffffffu, mx, 1));
            mx = fmaxf(mx, __shfl_xor_sync(0xffffffffu, mx, 2));
            float al = __expf(mold[hh] - mx);
            float s = 0.0f;
#pragma unroll
            for (int nf = 0; nf < 8; nf++)
#pragma unroll
                for (int e = 0; e < 2; e++) {
                    float p = __expf(sacc[nf][2 * hh + e] - mx);
                    sacc[nf][2 * hh + e] = p;
                    s += p;
                }
            s += __shfl_xor_sync(0xffffffffu, s, 1);
            s += __shfl_xor_sync(0xffffffffu, s, 2);
            mold[hh] = mx;
            lsum[hh] = lsum[hh] * al + s;
            alpha[hh] = al;
        }

        // ---- P -> bf16 hi/lo A-fragments ----
        uint32_t aPh[4][4], aPl[4][4];
#pragma unroll
        for (int kc = 0; kc < 4; kc++) {
            split2(sacc[2 * kc][0],     sacc[2 * kc][1],     aPh[kc][0], aPl[kc][0]);
            split2(sacc[2 * kc][2],     sacc[2 * kc][3],     aPh[kc][1], aPl[kc][1]);
            split2(sacc[2 * kc + 1][0], sacc[2 * kc + 1][1], aPh[kc][2], aPl[kc][2]);
            split2(sacc[2 * kc + 1][2], sacc[2 * kc + 1][3], aPh[kc][3], aPl[kc][3]);
        }

        // ---- rescale O ----
#pragma unroll
        for (int nf = 0; nf < 16; nf++) {
            oacc[nf][0] *= alpha[0]; oacc[nf][1] *= alpha[0];
            oacc[nf][2] *= alpha[1]; oacc[nf][3] *= alpha[1];
        }

        // ---- O += P V (3 terms; V via ldmatrix.trans) ----
#pragma unroll
        for (int kc = 0; kc < 4; kc++) {
#pragma unroll
            for (int dp = 0; dp < 8; dp++) {
                uint32_t r4[4];
                uint32_t vo = (uint32_t)(kc * 16 * FA_ROWB) + dp * 32 + aoff;
                ldsm4t(r4, sVh + vo);
                uint32_t bh0[2] = { r4[0], r4[1] }, bh1[2] = { r4[2], r4[3] };
                ldsm4t(r4, sVl + vo);
                uint32_t bl0[2] = { r4[0], r4[1] }, bl1[2] = { r4[2], r4[3] };
                mma16816(oacc[2 * dp],     aPh[kc], bh0);
                mma16816(oacc[2 * dp],     aPh[kc], bl0);
                mma16816(oacc[2 * dp],     aPl[kc], bh0);
                mma16816(oacc[2 * dp + 1], aPh[kc], bh1);
                mma16816(oacc[2 * dp + 1], aPh[kc], bl1);
                mma16816(oacc[2 * dp + 1], aPl[kc], bh1);
            }
        }
        __syncthreads();
    }

    // ---- epilogue ----
    float linv[2] = { 1.0f / lsum[0], 1.0f / lsum[1] };
#pragma unroll
    for (int nf = 0; nf < 16; nf++) {
#pragma unroll
        for (int hh = 0; hh < 2; hh++) {
            int rq = q0 + m0 + (lane >> 2) + 8 * hh;
            int col = nf * 8 + 2 * (lane & 3);
            float* p = ctx + ((size_t)(b * S_ + rq) * H_ + head) * HD_ + col;
            *(float2*)p = make_float2(oacc[nf][2 * hh] * linv[hh],
                                      oacc[nf][2 * hh + 1] * linv[hh]);
        }
    }
}

// ---------------------------------------------------------------------------
extern "C" void kernel_launch(void* const* d_in, const int* in_sizes, int n_in,
                              void* d_out, int out_size) {
    const float* x    = (const float*)d_in[0];
    const float* cs   = (const float*)d_in[2];
    const float* sn   = (const float*)d_in[3];
    const float* W_q  = (const float*)d_in[4];
    const float* W_k  = (const float*)d_in[5];
    const float* W_v  = (const float*)d_in[6];
    const float* W_o  = (const float*)d_in[7];
    const float* qnw  = (const float*)d_in[8];
    const float* knw  = (const float*)d_in[9];
    float* out = (float*)d_out;

    float *q, *k, *v, *ctx;
    cudaGetSymbolAddress((void**)&q,   g_q);
    cudaGetSymbolAddress((void**)&k,   g_k);
    cudaGetSymbolAddress((void**)&v,   g_v);
    cudaGetSymbolAddress((void**)&ctx, g_ctx);
    __nv_bfloat16 *xh, *xl, *ch, *cl, *wqh, *wql, *wkh, *wkl, *wvh, *wvl, *woh, *wol;
    __nv_bfloat16 *qhh, *qll, *khh, *kll, *vhh, *vll;
    cudaGetSymbolAddress((void**)&xh,  g_x_hi);   cudaGetSymbolAddress((void**)&xl,  g_x_lo);
    cudaGetSymbolAddress((void**)&ch,  g_ctx_hi); cudaGetSymbolAddress((void**)&cl,  g_ctx_lo);
    cudaGetSymbolAddress((void**)&wqh, g_wq_hi);  cudaGetSymbolAddress((void**)&wql, g_wq_lo);
    cudaGetSymbolAddress((void**)&wkh, g_wk_hi);  cudaGetSymbolAddress((void**)&wkl, g_wk_lo);
    cudaGetSymbolAddress((void**)&wvh, g_wv_hi);  cudaGetSymbolAddress((void**)&wvl, g_wv_lo);
    cudaGetSymbolAddress((void**)&woh, g_wo_hi);  cudaGetSymbolAddress((void**)&wol, g_wo_lo);
    cudaGetSymbolAddress((void**)&qhh, g_qhi);    cudaGetSymbolAddress((void**)&qll, g_qlo);
    cudaGetSymbolAddress((void**)&khh, g_khi);    cudaGetSymbolAddress((void**)&kll, g_klo);
    cudaGetSymbolAddress((void**)&vhh, g_vhi);    cudaGetSymbolAddress((void**)&vll, g_vlo);

    static int attr_set = 0;
    if (!attr_set) {
        cudaFuncSetAttribute(gemm_mma, cudaFuncAttributeMaxDynamicSharedMemorySize, GT_SMEM);
        cudaFuncSetAttribute(flash_mma, cudaFuncAttributeMaxDynamicSharedMemorySize, FA_SMEM);
        attr_set = 1;
    }

    const int M = B_ * S_;          // 4096
    const int NXY = M * D_ / 4;
    const int NW  = D_ * D_ / 4;
    const int NKV = KV_ * HD_ * D_ / 4;
    const int NQ  = M * H_ * HD_ / 4;    // == NXY
    const int NKVT = M * KV_ * HD_ / 4;

    // split inputs to (hi, lo) bf16
    split_bf16<<<(NXY + 255) / 256, 256>>>(x,   xh,  xl,  NXY);
    split_bf16<<<(NW  + 255) / 256, 256>>>(W_q, wqh, wql, NW);
    split_bf16<<<(NKV + 255) / 256, 256>>>(W_k, wkh, wkl, NKV);
    split_bf16<<<(NKV + 255) / 256, 256>>>(W_v, wvh, wvl, NKV);
    split_bf16<<<(NW  + 255) / 256, 256>>>(W_o, woh, wol, NW);

    // QKV projections
    {
        dim3 gq(D_ / 128, M / 128);
        gemm_mma<<<gq, 256, GT_SMEM>>>(xh, xl, wqh, wql, q, M, D_, D_);
        dim3 gk((KV_ * HD_) / 128, M / 128);
        gemm_mma<<<gk, 256, GT_SMEM>>>(xh, xl, wkh, wkl, k, M, KV_ * HD_, D_);
        gemm_mma<<<gk, 256, GT_SMEM>>>(xh, xl, wvh, wvl, v, M, KV_ * HD_, D_);
    }

    // RMSNorm + RoPE
    norm_rope<<<M * H_, 128>>>(q, qnw, cs, sn, H_);
    norm_rope<<<M * KV_, 128>>>(k, knw, cs, sn, KV_);

    // split q/k/v for tensor-core attention
    split_bf16<<<(NQ   + 255) / 256, 256>>>(q, qhh, qll, NQ);
    split_bf16<<<(NKVT + 255) / 256, 256>>>(k, khh, kll, NKVT);
    split_bf16<<<(NKVT + 255) / 256, 256>>>(v, vhh, vll, NKVT);

    // Attention (tensor core)
    {
        dim3 g(S_ / 128, H_, B_);
        flash_mma<<<g, 256, FA_SMEM>>>(qhh, qll, khh, kll, vhh, vll, ctx);
    }

    // Output projection
    split_bf16<<<(NXY + 255) / 256, 256>>>(ctx, ch, cl, NXY);
    {
        dim3 go(D_ / 128, M / 128);
        gemm_mma<<<go, 256, GT_SMEM>>>(ch, cl, woh, wol, out, M, D_, D_);
    }
}

// round 10
// speedup vs baseline: 3.5933x; 1.0097x over previous
#include <cuda_runtime.h>
#include <cuda_bf16.h>
#include <math.h>
#include <stdint.h>

#define B_  2
#define S_  2048
#define D_  2048
#define H_  16
#define KV_ 4
#define HD_ 128
#define G_  4
#define NQKV 3072                    // 2048 q + 512 k + 512 v

// ---------------- scratch (static device globals; no allocation allowed) ----
__device__ float g_qkv[(size_t)B_*S_*NQKV];                  // fused QKV fp32
__device__ __nv_bfloat16 g_x_hi[(size_t)B_*S_*D_],    g_x_lo[(size_t)B_*S_*D_];
__device__ __nv_bfloat16 g_ctx_hi[(size_t)B_*S_*D_],  g_ctx_lo[(size_t)B_*S_*D_];
__device__ __nv_bfloat16 g_wqkv_hi[(size_t)NQKV*D_],  g_wqkv_lo[(size_t)NQKV*D_];
__device__ __nv_bfloat16 g_wo_hi[(size_t)D_*D_],      g_wo_lo[(size_t)D_*D_];
// attention hi/lo buffers
__device__ __nv_bfloat16 g_qhi[(size_t)B_*S_*H_*HD_],  g_qlo[(size_t)B_*S_*H_*HD_];
__device__ __nv_bfloat16 g_khi[(size_t)B_*S_*KV_*HD_], g_klo[(size_t)B_*S_*KV_*HD_];
__device__ __nv_bfloat16 g_vhi[(size_t)B_*S_*KV_*HD_], g_vlo[(size_t)B_*S_*KV_*HD_];

// ---------------- ptx helpers (plain compute_103-safe only) -----------------
__device__ __forceinline__ uint32_t smem_u32(const void* p) {
    uint32_t a;
    asm("{ .reg .u64 t; cvta.to.shared.u64 t, %1; cvt.u32.u64 %0, t; }"
        : "=r"(a) : "l"(p));
    return a;
}
__device__ __forceinline__ void cpa16(uint32_t s, const void* g) {
    asm volatile("cp.async.cg.shared.global [%0], [%1], 16;"
                 :: "r"(s), "l"(g) : "memory");
}
__device__ __forceinline__ void cpa_commit() {
    asm volatile("cp.async.commit_group;" ::: "memory");
}
template<int N> __device__ __forceinline__ void cpa_wait() {
    asm volatile("cp.async.wait_group %0;" :: "n"(N) : "memory");
}
__device__ __forceinline__ void ldsm4(uint32_t* r, uint32_t addr) {
    asm volatile("ldmatrix.sync.aligned.m8n8.x4.shared.b16 {%0,%1,%2,%3}, [%4];"
                 : "=r"(r[0]), "=r"(r[1]), "=r"(r[2]), "=r"(r[3]) : "r"(addr));
}
__device__ __forceinline__ void ldsm4t(uint32_t* r, uint32_t addr) {
    asm volatile("ldmatrix.sync.aligned.m8n8.x4.trans.shared.b16 {%0,%1,%2,%3}, [%4];"
                 : "=r"(r[0]), "=r"(r[1]), "=r"(r[2]), "=r"(r[3]) : "r"(addr));
}
__device__ __forceinline__ void mma16816(float* c, const uint32_t* a, const uint32_t* b) {
    asm volatile(
        "mma.sync.aligned.m16n8k16.row.col.f32.bf16.bf16.f32 "
        "{%0,%1,%2,%3}, {%4,%5,%6,%7}, {%8,%9}, {%0,%1,%2,%3};"
        : "+f"(c[0]), "+f"(c[1]), "+f"(c[2]), "+f"(c[3])
        : "r"(a[0]), "r"(a[1]), "r"(a[2]), "r"(a[3]), "r"(b[0]), "r"(b[1]));
}
__device__ __forceinline__ void split2(float a, float b, uint32_t& hi, uint32_t& lo) {
    __nv_bfloat162 h = __floats2bfloat162_rn(a, b);
    hi = *(uint32_t*)&h;
    float ra = a - __bfloat162float(h.x);
    float rb = b - __bfloat162float(h.y);
    __nv_bfloat162 l = __floats2bfloat162_rn(ra, rb);
    lo = *(uint32_t*)&l;
}

// ---------------------------------------------------------------------------
// split fp32 -> (hi, lo) bf16 (contiguous)
// ---------------------------------------------------------------------------
__global__ __launch_bounds__(256) void split_bf16(const float* __restrict__ s,
                                                  __nv_bfloat16* __restrict__ hi,
                                                  __nv_bfloat16* __restrict__ lo,
                                                  int n4) {
    int i = blockIdx.x * 256 + threadIdx.x;
    if (i >= n4) return;
    float4 v = ((const float4*)s)[i];
    __nv_bfloat16 h0 = __float2bfloat16(v.x), h1 = __float2bfloat16(v.y);
    __nv_bfloat16 h2 = __float2bfloat16(v.z), h3 = __float2bfloat16(v.w);
    __nv_bfloat16 l0 = __float2bfloat16(v.x - __bfloat162float(h0));
    __nv_bfloat16 l1 = __float2bfloat16(v.y - __bfloat162float(h1));
    __nv_bfloat16 l2 = __float2bfloat16(v.z - __bfloat162float(h2));
    __nv_bfloat16 l3 = __float2bfloat16(v.w - __bfloat162float(h3));
    __nv_bfloat162* hp = (__nv_bfloat162*)(hi + (size_t)i * 4);
    __nv_bfloat162* lp = (__nv_bfloat162*)(lo + (size_t)i * 4);
    hp[0] = __nv_bfloat162(h0, h1); hp[1] = __nv_bfloat162(h2, h3);
    lp[0] = __nv_bfloat162(l0, l1); lp[1] = __nv_bfloat162(l2, l3);
}

// ---------------------------------------------------------------------------
// mma.sync split-bf16 GEMM (unchanged)
// ---------------------------------------------------------------------------
#define BKC 32
#define TILEB (128 * 40 * 2)
#define STAGEB (4 * TILEB)
#define STAGES 3
#define GT_SMEM (STAGES * STAGEB)

__global__ __launch_bounds__(256, 1) void gemm_mma(
    const __nv_bfloat16* __restrict__ Ahi, const __nv_bfloat16* __restrict__ Alo,
    const __nv_bfloat16* __restrict__ Bhi, const __nv_bfloat16* __restrict__ Blo,
    float* __restrict__ C, int M, int N, int K)
{
    extern __shared__ char sm[];
    const uint32_t sb = smem_u32(sm);
    const int tid = threadIdx.x;
    const int wid = tid >> 5, lane = tid & 31;
    const int wm = (wid >> 2) * 64;
    const int wn = (wid & 3) * 32;
    const int rowBase = blockIdx.y * 128;
    const int colBase = blockIdx.x * 128;
    const int NC = K / BKC;

    const __nv_bfloat16* srcs[4] = {
        Ahi + (size_t)rowBase * K, Alo + (size_t)rowBase * K,
        Bhi + (size_t)colBase * K, Blo + (size_t)colBase * K };

    auto load_chunk = [&](int c) {
        uint32_t stb = sb + (uint32_t)(c % STAGES) * STAGEB;
#pragma unroll
        for (int j = 0; j < 8; j++) {
            int idx = tid + j * 256;
            int t4 = idx >> 9;
            int e  = idx & 511;
            int r  = e >> 2, c4 = e & 3;
            uint32_t dst = stb + (uint32_t)t4 * TILEB + (uint32_t)(r * 80 + c4 * 16);
            cpa16(dst, srcs[t4] + (size_t)c * BKC + (size_t)r * K + c4 * 8);
        }
        cpa_commit();
    };

    const uint32_t aoff = (uint32_t)((lane & 15) * 80 + (lane >> 4) * 16);
    const uint32_t boff = (uint32_t)(((lane & 7) + 8 * (lane >> 4)) * 80 +
                                     ((lane >> 3) & 1) * 16);

    float acc[4][4][4];
#pragma unroll
    for (int mi = 0; mi < 4; mi++)
#pragma unroll
        for (int nj = 0; nj < 4; nj++)
#pragma unroll
            for (int e = 0; e < 4; e++) acc[mi][nj][e] = 0.0f;

    load_chunk(0);
    load_chunk(1);
    load_chunk(2);

    for (int c = 0; c < NC; c++) {
        cpa_wait<2>();
        __syncthreads();

        uint32_t stb = sb + (uint32_t)(c % STAGES) * STAGEB;
        const uint32_t sAhi = stb, sAlo = stb + TILEB;
        const uint32_t sBhi = stb + 2 * TILEB, sBlo = stb + 3 * TILEB;

#pragma unroll
        for (int ks = 0; ks < 2; ks++) {
            uint32_t kb = (uint32_t)(32 * ks);
            uint32_t bhi[4][2], blo[4][2];
#pragma unroll
            for (int njp = 0; njp < 2; njp++) {
                uint32_t r4[4];
                uint32_t bo = (uint32_t)((wn + 16 * njp) * 80) + kb + boff;
                ldsm4(r4, sBhi + bo);
                bhi[2 * njp][0] = r4[0]; bhi[2 * njp][1] = r4[1];
                bhi[2 * njp + 1][0] = r4[2]; bhi[2 * njp + 1][1] = r4[3];
                ldsm4(r4, sBlo + bo);
                blo[2 * njp][0] = r4[0]; blo[2 * njp][1] = r4[1];
                blo[2 * njp + 1][0] = r4[2]; blo[2 * njp + 1][1] = r4[3];
            }
#pragma unroll
            for (int mi = 0; mi < 4; mi++) {
                uint32_t ahi[4], alo[4];
                uint32_t ao = (uint32_t)((wm + 16 * mi) * 80) + kb + aoff;
                ldsm4(ahi, sAhi + ao);
                ldsm4(alo, sAlo + ao);
#pragma unroll
                for (int nj = 0; nj < 4; nj++) {
                    mma16816(acc[mi][nj], ahi, bhi[nj]);
                    mma16816(acc[mi][nj], ahi, blo[nj]);
                    mma16816(acc[mi][nj], alo, bhi[nj]);
                }
            }
        }
        __syncthreads();
        if (c + 3 < NC) load_chunk(c + 3);
        else cpa_commit();
    }

    const int r0 = rowBase + wm + (lane >> 2);
    const int c0 = colBase + wn + 2 * (lane & 3);
#pragma unroll
    for (int mi = 0; mi < 4; mi++) {
#pragma unroll
        for (int nj = 0; nj < 4; nj++) {
            float* p0 = C + (size_t)(r0 + 16 * mi) * N + c0 + 8 * nj;
            float* p1 = p0 + (size_t)8 * N;
            *(float2*)p0 = make_float2(acc[mi][nj][0], acc[mi][nj][1]);
            *(float2*)p1 = make_float2(acc[mi][nj][2], acc[mi][nj][3]);
        }
    }
}

// ---------------------------------------------------------------------------
// Fused RMSNorm + RoPE + hi/lo split.
// Reads fp32 from strided QKV buffer, writes bf16 hi/lo attention layout.
// One block (128 thr) per (m, head) row; row = m*nh + h.
// ---------------------------------------------------------------------------
__global__ __launch_bounds__(128) void norm_rope_split(
    const float* __restrict__ src, int srcOff,
    __nv_bfloat16* __restrict__ hi, __nv_bfloat16* __restrict__ lo,
    const float* __restrict__ w,
    const float* __restrict__ cs, const float* __restrict__ sn, int nh)
{
    const int row = blockIdx.x;            // m*nh + h
    const int m = row / nh, h = row - m * nh;
    const int s = m % S_;
    const int i = threadIdx.x;
    const float* p = src + (size_t)m * NQKV + srcOff + h * HD_;
    float v = p[i];
    float ss = v * v;
#pragma unroll
    for (int o = 16; o; o >>= 1) ss += __shfl_xor_sync(0xffffffff, ss, o);
    __shared__ float wsum[4];
    __shared__ float nbuf[HD_];
    if ((i & 31) == 0) wsum[i >> 5] = ss;
    __syncthreads();
    float tot = wsum[0] + wsum[1] + wsum[2] + wsum[3];
    float rstd = rsqrtf(tot * (1.0f / HD_) + 1e-5f);
    float n = v * rstd * w[i];
    nbuf[i] = n;
    __syncthreads();
    float rot = (i < 64) ? -nbuf[i + 64] : nbuf[i - 64];
    float outv = n * cs[s * HD_ + i] + rot * sn[s * HD_ + i];
    __nv_bfloat16 hb = __float2bfloat16(outv);
    __nv_bfloat16 lb = __float2bfloat16(outv - __bfloat162float(hb));
    hi[(size_t)row * HD_ + i] = hb;
    lo[(size_t)row * HD_ + i] = lb;
}

// ---------------------------------------------------------------------------
// Strided split for V: reads fp32 V columns of QKV buffer, writes hi/lo.
// ---------------------------------------------------------------------------
__global__ __launch_bounds__(256) void split_v(const float* __restrict__ src,
                                               __nv_bfloat16* __restrict__ hi,
                                               __nv_bfloat16* __restrict__ lo) {
    int i = blockIdx.x * 256 + threadIdx.x;          // over M*512/4
    int m = i >> 7, c = i & 127;                     // 128 float4 per row
    float4 v = *(const float4*)(src + (size_t)m * NQKV + 2560 + c * 4);
    __nv_bfloat16 h0 = __float2bfloat16(v.x), h1 = __float2bfloat16(v.y);
    __nv_bfloat16 h2 = __float2bfloat16(v.z), h3 = __float2bfloat16(v.w);
    __nv_bfloat16 l0 = __float2bfloat16(v.x - __bfloat162float(h0));
    __nv_bfloat16 l1 = __float2bfloat16(v.y - __bfloat162float(h1));
    __nv_bfloat16 l2 = __float2bfloat16(v.z - __bfloat162float(h2));
    __nv_bfloat16 l3 = __float2bfloat16(v.w - __bfloat162float(h3));
    size_t o = (size_t)m * 512 + c * 4;
    __nv_bfloat162* hp = (__nv_bfloat162*)(hi + o);
    __nv_bfloat162* lp = (__nv_bfloat162*)(lo + o);
    hp[0] = __nv_bfloat162(h0, h1); hp[1] = __nv_bfloat162(h2, h3);
    lp[0] = __nv_bfloat162(l0, l1); lp[1] = __nv_bfloat162(l2, l3);
}

// ---------------------------------------------------------------------------
// mma.sync split-bf16 causal GQA flash attention.
// BQ=128, BKV=64, HD=128. 8 warps x 16 q-rows. Double-buffered K/V.
// Epilogue writes ctx directly as bf16 hi/lo (fused split).
// ---------------------------------------------------------------------------
#define FA_ROWB 272
#define FA_QT  (128 * FA_ROWB)
#define FA_KVT (64 * FA_ROWB)
#define FA_STAGE (4 * FA_KVT)
#define FA_SMEM (2 * FA_QT + 2 * FA_STAGE)

__global__ __launch_bounds__(256, 1) void flash_mma(
    const __nv_bfloat16* __restrict__ qh, const __nv_bfloat16* __restrict__ ql,
    const __nv_bfloat16* __restrict__ kh, const __nv_bfloat16* __restrict__ kl,
    const __nv_bfloat16* __restrict__ vh, const __nv_bfloat16* __restrict__ vl,
    __nv_bfloat16* __restrict__ ch, __nv_bfloat16* __restrict__ cl)
{
    extern __shared__ char sm[];
    const uint32_t sb  = smem_u32(sm);
    const uint32_t sQh = sb, sQl = sb + FA_QT;
    const uint32_t sKV0 = sb + 2 * FA_QT;

    const int b = blockIdx.z, head = blockIdx.y;
    const int qt = gridDim.x - 1 - blockIdx.x;
    const int q0 = qt * 128;
    const int kvh = head / G_;
    const int tid = threadIdx.x, wid = tid >> 5, lane = tid & 31;
    const int m0 = wid * 16;
    const float scale = 0.08838834764831845f;

    {
        const __nv_bfloat16* srcs[2] = { qh, ql };
#pragma unroll
        for (int j = 0; j < 16; j++) {
            int idx = tid + j * 256;
            int t = idx >> 11;
            int e = idx & 2047;
            int r = e >> 4, c = e & 15;
            uint32_t dst = (t ? sQl : sQh) + (uint32_t)(r * FA_ROWB + c * 16);
            cpa16(dst, srcs[t] + ((size_t)(b * S_ + q0 + r) * H_ + head) * HD_ + c * 8);
        }
    }
    auto load_kv = [&](int kt) {
        uint32_t st = sKV0 + (uint32_t)(kt & 1) * FA_STAGE;
        const __nv_bfloat16* srcs[4] = { kh, kl, vh, vl };
#pragma unroll
        for (int j = 0; j < 16; j++) {
            int idx = tid + j * 256;
            int t4 = idx >> 10;
            int e = idx & 1023;
            int r = e >> 4, c = e & 15;
            uint32_t dst = st + (uint32_t)t4 * FA_KVT + (uint32_t)(r * FA_ROWB + c * 16);
            cpa16(dst, srcs[t4] + ((size_t)(b * S_ + kt * 64 + r) * KV_ + kvh) * HD_ + c * 8);
        }
    };
    load_kv(0);
    cpa_commit();

    const uint32_t aoff = (uint32_t)((lane & 15) * FA_ROWB + (lane >> 4) * 16);
    const uint32_t boff = (uint32_t)(((lane & 7) + 8 * (lane >> 4)) * FA_ROWB +
                                     ((lane >> 3) & 1) * 16);

    float oacc[16][4];
#pragma unroll
    for (int nf = 0; nf < 16; nf++)
#pragma unroll
        for (int e = 0; e < 4; e++) oacc[nf][e] = 0.0f;
    float mold[2] = { -1e30f, -1e30f }, lsum[2] = { 0.0f, 0.0f };

    const int nkv = 2 * (qt + 1);
    for (int kt = 0; kt < nkv; kt++) {
        if (kt + 1 < nkv) { load_kv(kt + 1); cpa_commit(); cpa_wait<1>(); }
        else cpa_wait<0>();
        __syncthreads();

        uint32_t st = sKV0 + (uint32_t)(kt & 1) * FA_STAGE;
        uint32_t sKh = st, sKl = st + FA_KVT;
        uint32_t sVh = st + 2 * FA_KVT, sVl = st + 3 * FA_KVT;

        float sacc[8][4];
#pragma unroll
        for (int nf = 0; nf < 8; nf++)
#pragma unroll
            for (int e = 0; e < 4; e++) sacc[nf][e] = 0.0f;
#pragma unroll
        for (int ks = 0; ks < 8; ks++) {
            uint32_t bh[8][2], bl[8][2];
#pragma unroll
            for (int njp = 0; njp < 4; njp++) {
                uint32_t r4[4];
                uint32_t bo = (uint32_t)(16 * njp * FA_ROWB) + ks * 32 + boff;
                ldsm4(r4, sKh + bo);
                bh[2 * njp][0] = r4[0]; bh[2 * njp][1] = r4[1];
                bh[2 * njp + 1][0] = r4[2]; bh[2 * njp + 1][1] = r4[3];
                ldsm4(r4, sKl + bo);
                bl[2 * njp][0] = r4[0]; bl[2 * njp][1] = r4[1];
                bl[2 * njp + 1][0] = r4[2]; bl[2 * njp + 1][1] = r4[3];
            }
            uint32_t ah[4], al[4];
            uint32_t ao = (uint32_t)(m0 * FA_ROWB) + ks * 32 + aoff;
            ldsm4(ah, sQh + ao);
            ldsm4(al, sQl + ao);
#pragma unroll
            for (int nf = 0; nf < 8; nf++) {
                mma16816(sacc[nf], ah, bh[nf]);
                mma16816(sacc[nf], ah, bl[nf]);
                mma16816(sacc[nf], al, bh[nf]);
            }
        }

        const bool diag = (kt >= 2 * qt);
        float alpha[2];
#pragma unroll
        for (int hh = 0; hh < 2; hh++) {
            int rowg = q0 + m0 + (lane >> 2) + 8 * hh;
            float mx = mold[hh];
#pragma unroll
            for (int nf = 0; nf < 8; nf++)
#pragma unroll
                for (int e = 0; e < 2; e++) {
                    float v = sacc[nf][2 * hh + e] * scale;
                    if (diag) {
                        int colg = kt * 64 + nf * 8 + 2 * (lane & 3) + e;
                        if (colg > rowg) v = -1e30f;
                    }
                    sacc[nf][2 * hh + e] = v;
                    mx = fmaxf(mx, v);
                }
            mx = fmaxf(mx, __shfl_xor_sync(0xffffffffu, mx, 1));
            mx = fmaxf(mx, __shfl_xor_sync(0xffffffffu, mx, 2));
            float al = __expf(mold[hh] - mx);
            float s = 0.0f;
#pragma unroll
            for (int nf = 0; nf < 8; nf++)
#pragma unroll
                for (int e = 0; e < 2; e++) {
                    float p = __expf(sacc[nf][2 * hh + e] - mx);
                    sacc[nf][2 * hh + e] = p;
                    s += p;
                }
            s += __shfl_xor_sync(0xffffffffu, s, 1);
            s += __shfl_xor_sync(0xffffffffu, s, 2);
            mold[hh] = mx;
            lsum[hh] = lsum[hh] * al + s;
            alpha[hh] = al;
        }

        uint32_t aPh[4][4], aPl[4][4];
#pragma unroll
        for (int kc = 0; kc < 4; kc++) {
            split2(sacc[2 * kc][0],     sacc[2 * kc][1],     aPh[kc][0], aPl[kc][0]);
            split2(sacc[2 * kc][2],     sacc[2 * kc][3],     aPh[kc][1], aPl[kc][1]);
            split2(sacc[2 * kc + 1][0], sacc[2 * kc + 1][1], aPh[kc][2], aPl[kc][2]);
            split2(sacc[2 * kc + 1][2], sacc[2 * kc + 1][3], aPh[kc][3], aPl[kc][3]);
        }

#pragma unroll
        for (int nf = 0; nf < 16; nf++) {
            oacc[nf][0] *= alpha[0]; oacc[nf][1] *= alpha[0];
            oacc[nf][2] *= alpha[1]; oacc[nf][3] *= alpha[1];
        }

#pragma unroll
        for (int kc = 0; kc < 4; kc++) {
#pragma unroll
            for (int dp = 0; dp < 8; dp++) {
                uint32_t r4[4];
                uint32_t vo = (uint32_t)(kc * 16 * FA_ROWB) + dp * 32 + aoff;
                ldsm4t(r4, sVh + vo);
                uint32_t bh0[2] = { r4[0], r4[1] }, bh1[2] = { r4[2], r4[3] };
                ldsm4t(r4, sVl + vo);
                uint32_t bl0[2] = { r4[0], r4[1] }, bl1[2] = { r4[2], r4[3] };
                mma16816(oacc[2 * dp],     aPh[kc], bh0);
                mma16816(oacc[2 * dp],     aPh[kc], bl0);
                mma16816(oacc[2 * dp],     aPl[kc], bh0);
                mma16816(oacc[2 * dp + 1], aPh[kc], bh1);
                mma16816(oacc[2 * dp + 1], aPh[kc], bl1);
                mma16816(oacc[2 * dp + 1], aPl[kc], bh1);
            }
        }
        __syncthreads();
    }

    // ---- epilogue: normalize, split to bf16 hi/lo, store (fused split) ----
    float linv[2] = { 1.0f / lsum[0], 1.0f / lsum[1] };
#pragma unroll
    for (int nf = 0; nf < 16; nf++) {
#pragma unroll
        for (int hh = 0; hh < 2; hh++) {
            int rq = q0 + m0 + (lane >> 2) + 8 * hh;
            int col = head * HD_ + nf * 8 + 2 * (lane & 3);
            float v0 = oacc[nf][2 * hh] * linv[hh];
            float v1 = oacc[nf][2 * hh + 1] * linv[hh];
            uint32_t hi, lo;
            split2(v0, v1, hi, lo);
            size_t o = (size_t)(b * S_ + rq) * D_ + col;
            *(uint32_t*)(ch + o) = hi;
            *(uint32_t*)(cl + o) = lo;
        }
    }
}

// ---------------------------------------------------------------------------
extern "C" void kernel_launch(void* const* d_in, const int* in_sizes, int n_in,
                              void* d_out, int out_size) {
    const float* x    = (const float*)d_in[0];
    const float* cs   = (const float*)d_in[2];
    const float* sn   = (const float*)d_in[3];
    const float* W_q  = (const float*)d_in[4];
    const float* W_k  = (const float*)d_in[5];
    const float* W_v  = (const float*)d_in[6];
    const float* W_o  = (const float*)d_in[7];
    const float* qnw  = (const float*)d_in[8];
    const float* knw  = (const float*)d_in[9];
    float* out = (float*)d_out;

    float* qkv;
    cudaGetSymbolAddress((void**)&qkv, g_qkv);
    __nv_bfloat16 *xh, *xl, *ch, *cl, *wqkvh, *wqkvl, *woh, *wol;
    __nv_bfloat16 *qhh, *qll, *khh, *kll, *vhh, *vll;
    cudaGetSymbolAddress((void**)&xh,    g_x_hi);    cudaGetSymbolAddress((void**)&xl,    g_x_lo);
    cudaGetSymbolAddress((void**)&ch,    g_ctx_hi);  cudaGetSymbolAddress((void**)&cl,    g_ctx_lo);
    cudaGetSymbolAddress((void**)&wqkvh, g_wqkv_hi); cudaGetSymbolAddress((void**)&wqkvl, g_wqkv_lo);
    cudaGetSymbolAddress((void**)&woh,   g_wo_hi);   cudaGetSymbolAddress((void**)&wol,   g_wo_lo);
    cudaGetSymbolAddress((void**)&qhh,   g_qhi);     cudaGetSymbolAddress((void**)&qll,   g_qlo);
    cudaGetSymbolAddress((void**)&khh,   g_khi);     cudaGetSymbolAddress((void**)&kll,   g_klo);
    cudaGetSymbolAddress((void**)&vhh,   g_vhi);     cudaGetSymbolAddress((void**)&vll,   g_vlo);

    static int attr_set = 0;
    if (!attr_set) {
        cudaFuncSetAttribute(gemm_mma, cudaFuncAttributeMaxDynamicSharedMemorySize, GT_SMEM);
        cudaFuncSetAttribute(flash_mma, cudaFuncAttributeMaxDynamicSharedMemorySize, FA_SMEM);
        attr_set = 1;
    }

    const int M = B_ * S_;              // 4096
    const int NXY = M * D_ / 4;
    const int NW  = D_ * D_ / 4;        // Wq / Wo quads
    const int NKW = KV_ * HD_ * D_ / 4; // Wk / Wv quads

    // split inputs to (hi, lo) bf16; weights go into combined QKV buffer
    split_bf16<<<(NXY + 255) / 256, 256>>>(x,   xh,  xl,  NXY);
    split_bf16<<<(NW  + 255) / 256, 256>>>(W_q, wqkvh,                          wqkvl,                          NW);
    split_bf16<<<(NKW + 255) / 256, 256>>>(W_k, wqkvh + (size_t)D_ * D_,        wqkvl + (size_t)D_ * D_,        NKW);
    split_bf16<<<(NKW + 255) / 256, 256>>>(W_v, wqkvh + (size_t)(D_ + 512) * D_, wqkvl + (size_t)(D_ + 512) * D_, NKW);
    split_bf16<<<(NW  + 255) / 256, 256>>>(W_o, woh, wol, NW);

    // Fused QKV projection (one GEMM, N=3072)
    {
        dim3 g(NQKV / 128, M / 128);
        gemm_mma<<<g, 256, GT_SMEM>>>(xh, xl, wqkvh, wqkvl, qkv, M, NQKV, D_);
    }

    // Fused RMSNorm + RoPE + split (q, k), plain split (v)
    norm_rope_split<<<M * H_, 128>>>(qkv, 0,    qhh, qll, qnw, cs, sn, H_);
    norm_rope_split<<<M * KV_, 128>>>(qkv, 2048, khh, kll, knw, cs, sn, KV_);
    split_v<<<M * 128 / 256, 256>>>(qkv, vhh, vll);

    // Attention (tensor core) — epilogue writes ctx hi/lo directly
    {
        dim3 g(S_ / 128, H_, B_);
        flash_mma<<<g, 256, FA_SMEM>>>(qhh, qll, khh, kll, vhh, vll, ch, cl);
    }

    // Output projection
    {
        dim3 go(D_ / 128, M / 128);
        gemm_mma<<<go, 256, GT_SMEM>>>(ch, cl, woh, wol, out, M, D_, D_);
    }
}

// round 14
// speedup vs baseline: 3.6170x; 1.0066x over previous
#include <cuda_runtime.h>
#include <cuda_bf16.h>
#include <math.h>
#include <stdint.h>

#define B_  2
#define S_  2048
#define D_  2048
#define H_  16
#define KV_ 4
#define HD_ 128
#define G_  4
#define NQKV 3072                    // 2048 q + 512 k + 512 v

// ---------------- scratch (static device globals; no allocation allowed) ----
__device__ float g_qkv[(size_t)B_*S_*NQKV];                  // fused QKV fp32
__device__ __nv_bfloat16 g_x_hi[(size_t)B_*S_*D_],    g_x_lo[(size_t)B_*S_*D_];
__device__ __nv_bfloat16 g_ctx_hi[(size_t)B_*S_*D_],  g_ctx_lo[(size_t)B_*S_*D_];
__device__ __nv_bfloat16 g_wqkv_hi[(size_t)NQKV*D_],  g_wqkv_lo[(size_t)NQKV*D_];
__device__ __nv_bfloat16 g_wo_hi[(size_t)D_*D_],      g_wo_lo[(size_t)D_*D_];
// attention hi/lo buffers
__device__ __nv_bfloat16 g_qhi[(size_t)B_*S_*H_*HD_],  g_qlo[(size_t)B_*S_*H_*HD_];
__device__ __nv_bfloat16 g_khi[(size_t)B_*S_*KV_*HD_], g_klo[(size_t)B_*S_*KV_*HD_];
__device__ __nv_bfloat16 g_vhi[(size_t)B_*S_*KV_*HD_], g_vlo[(size_t)B_*S_*KV_*HD_];

// ---------------- ptx helpers (plain compute_103-safe only) -----------------
__device__ __forceinline__ uint32_t smem_u32(const void* p) {
    uint32_t a;
    asm("{ .reg .u64 t; cvta.to.shared.u64 t, %1; cvt.u32.u64 %0, t; }"
        : "=r"(a) : "l"(p));
    return a;
}
__device__ __forceinline__ void cpa16(uint32_t s, const void* g) {
    asm volatile("cp.async.cg.shared.global [%0], [%1], 16;"
                 :: "r"(s), "l"(g) : "memory");
}
__device__ __forceinline__ void cpa_commit() {
    asm volatile("cp.async.commit_group;" ::: "memory");
}
template<int N> __device__ __forceinline__ void cpa_wait() {
    asm volatile("cp.async.wait_group %0;" :: "n"(N) : "memory");
}
__device__ __forceinline__ void ldsm4(uint32_t* r, uint32_t addr) {
    asm volatile("ldmatrix.sync.aligned.m8n8.x4.shared.b16 {%0,%1,%2,%3}, [%4];"
                 : "=r"(r[0]), "=r"(r[1]), "=r"(r[2]), "=r"(r[3]) : "r"(addr));
}
__device__ __forceinline__ void ldsm4t(uint32_t* r, uint32_t addr) {
    asm volatile("ldmatrix.sync.aligned.m8n8.x4.trans.shared.b16 {%0,%1,%2,%3}, [%4];"
                 : "=r"(r[0]), "=r"(r[1]), "=r"(r[2]), "=r"(r[3]) : "r"(addr));
}
__device__ __forceinline__ void mma16816(float* c, const uint32_t* a, const uint32_t* b) {
    asm volatile(
        "mma.sync.aligned.m16n8k16.row.col.f32.bf16.bf16.f32 "
        "{%0,%1,%2,%3}, {%4,%5,%6,%7}, {%8,%9}, {%0,%1,%2,%3};"
        : "+f"(c[0]), "+f"(c[1]), "+f"(c[2]), "+f"(c[3])
        : "r"(a[0]), "r"(a[1]), "r"(a[2]), "r"(a[3]), "r"(b[0]), "r"(b[1]));
}
__device__ __forceinline__ void split2(float a, float b, uint32_t& hi, uint32_t& lo) {
    __nv_bfloat162 h = __floats2bfloat162_rn(a, b);
    hi = *(uint32_t*)&h;
    float ra = a - __bfloat162float(h.x);
    float rb = b - __bfloat162float(h.y);
    __nv_bfloat162 l = __floats2bfloat162_rn(ra, rb);
    lo = *(uint32_t*)&l;
}

// ---------------------------------------------------------------------------
// split fp32 -> (hi, lo) bf16 (contiguous)
// ---------------------------------------------------------------------------
__global__ __launch_bounds__(256) void split_bf16(const float* __restrict__ s,
                                                  __nv_bfloat16* __restrict__ hi,
                                                  __nv_bfloat16* __restrict__ lo,
                                                  int n4) {
    int i = blockIdx.x * 256 + threadIdx.x;
    if (i >= n4) return;
    float4 v = ((const float4*)s)[i];
    __nv_bfloat16 h0 = __float2bfloat16(v.x), h1 = __float2bfloat16(v.y);
    __nv_bfloat16 h2 = __float2bfloat16(v.z), h3 = __float2bfloat16(v.w);
    __nv_bfloat16 l0 = __float2bfloat16(v.x - __bfloat162float(h0));
    __nv_bfloat16 l1 = __float2bfloat16(v.y - __bfloat162float(h1));
    __nv_bfloat16 l2 = __float2bfloat16(v.z - __bfloat162float(h2));
    __nv_bfloat16 l3 = __float2bfloat16(v.w - __bfloat162float(h3));
    __nv_bfloat162* hp = (__nv_bfloat162*)(hi + (size_t)i * 4);
    __nv_bfloat162* lp = (__nv_bfloat162*)(lo + (size_t)i * 4);
    hp[0] = __nv_bfloat162(h0, h1); hp[1] = __nv_bfloat162(h2, h3);
    lp[0] = __nv_bfloat162(l0, l1); lp[1] = __nv_bfloat162(l2, l3);
}

// ---------------------------------------------------------------------------
// mma.sync split-bf16 GEMM.
// 128x128 tile, BK=32, 4-stage cp.async pipeline (single sync per chunk),
// 8 warps (2m x 4n), warp tile 64x32, term-major MMA ordering (hh,hl,lh)
// to break accumulator RAW chains.
// ---------------------------------------------------------------------------
#define BKC 32
#define TILEB (128 * 40 * 2)
#define STAGEB (4 * TILEB)
#define STAGES 4
#define GT_SMEM (STAGES * STAGEB)          // 163840 B

__global__ __launch_bounds__(256, 1) void gemm_mma(
    const __nv_bfloat16* __restrict__ Ahi, const __nv_bfloat16* __restrict__ Alo,
    const __nv_bfloat16* __restrict__ Bhi, const __nv_bfloat16* __restrict__ Blo,
    float* __restrict__ C, int M, int N, int K)
{
    extern __shared__ char sm[];
    const uint32_t sb = smem_u32(sm);
    const int tid = threadIdx.x;
    const int wid = tid >> 5, lane = tid & 31;
    const int wm = (wid >> 2) * 64;
    const int wn = (wid & 3) * 32;
    const int rowBase = blockIdx.y * 128;
    const int colBase = blockIdx.x * 128;
    const int NC = K / BKC;

    const __nv_bfloat16* srcs[4] = {
        Ahi + (size_t)rowBase * K, Alo + (size_t)rowBase * K,
        Bhi + (size_t)colBase * K, Blo + (size_t)colBase * K };

    auto load_chunk = [&](int c) {
        uint32_t stb = sb + (uint32_t)(c & (STAGES - 1)) * STAGEB;
#pragma unroll
        for (int j = 0; j < 8; j++) {
            int idx = tid + j * 256;
            int t4 = idx >> 9;
            int e  = idx & 511;
            int r  = e >> 2, c4 = e & 3;
            uint32_t dst = stb + (uint32_t)t4 * TILEB + (uint32_t)(r * 80 + c4 * 16);
            cpa16(dst, srcs[t4] + (size_t)c * BKC + (size_t)r * K + c4 * 8);
        }
        cpa_commit();
    };

    const uint32_t aoff = (uint32_t)((lane & 15) * 80 + (lane >> 4) * 16);
    const uint32_t boff = (uint32_t)(((lane & 7) + 8 * (lane >> 4)) * 80 +
                                     ((lane >> 3) & 1) * 16);

    float acc[4][4][4];
#pragma unroll
    for (int mi = 0; mi < 4; mi++)
#pragma unroll
        for (int nj = 0; nj < 4; nj++)
#pragma unroll
            for (int e = 0; e < 4; e++) acc[mi][nj][e] = 0.0f;

    load_chunk(0);
    load_chunk(1);
    load_chunk(2);

    for (int c = 0; c < NC; c++) {
        cpa_wait<2>();
        __syncthreads();                  // all warps done with chunk c-1
        if (c + 3 < NC) load_chunk(c + 3);
        else cpa_commit();                // keep group accounting aligned

        uint32_t stb = sb + (uint32_t)(c & (STAGES - 1)) * STAGEB;
        const uint32_t sAhi = stb, sAlo = stb + TILEB;
        const uint32_t sBhi = stb + 2 * TILEB, sBlo = stb + 3 * TILEB;

#pragma unroll
        for (int ks = 0; ks < 2; ks++) {
            uint32_t kb = (uint32_t)(32 * ks);
            uint32_t bhi[4][2], blo[4][2];
#pragma unroll
            for (int njp = 0; njp < 2; njp++) {
                uint32_t r4[4];
                uint32_t bo = (uint32_t)((wn + 16 * njp) * 80) + kb + boff;
                ldsm4(r4, sBhi + bo);
                bhi[2 * njp][0] = r4[0]; bhi[2 * njp][1] = r4[1];
                bhi[2 * njp + 1][0] = r4[2]; bhi[2 * njp + 1][1] = r4[3];
                ldsm4(r4, sBlo + bo);
                blo[2 * njp][0] = r4[0]; blo[2 * njp][1] = r4[1];
                blo[2 * njp + 1][0] = r4[2]; blo[2 * njp + 1][1] = r4[3];
            }
            uint32_t ahi[4][4], alo[4][4];
#pragma unroll
            for (int mi = 0; mi < 4; mi++) {
                uint32_t ao = (uint32_t)((wm + 16 * mi) * 80) + kb + aoff;
                ldsm4(ahi[mi], sAhi + ao);
                ldsm4(alo[mi], sAlo + ao);
            }
            // term-major: 16 independent MMAs between accumulator reuses
#pragma unroll
            for (int mi = 0; mi < 4; mi++)
#pragma unroll
                for (int nj = 0; nj < 4; nj++)
                    mma16816(acc[mi][nj], ahi[mi], bhi[nj]);
#pragma unroll
            for (int mi = 0; mi < 4; mi++)
#pragma unroll
                for (int nj = 0; nj < 4; nj++)
                    mma16816(acc[mi][nj], ahi[mi], blo[nj]);
#pragma unroll
            for (int mi = 0; mi < 4; mi++)
#pragma unroll
                for (int nj = 0; nj < 4; nj++)
                    mma16816(acc[mi][nj], alo[mi], bhi[nj]);
        }
        // no tail barrier: 4-stage ring means the next load target was
        // consumed two chunks ago; the top barrier orders it.
    }

    const int r0 = rowBase + wm + (lane >> 2);
    const int c0 = colBase + wn + 2 * (lane & 3);
#pragma unroll
    for (int mi = 0; mi < 4; mi++) {
#pragma unroll
        for (int nj = 0; nj < 4; nj++) {
            float* p0 = C + (size_t)(r0 + 16 * mi) * N + c0 + 8 * nj;
            float* p1 = p0 + (size_t)8 * N;
            *(float2*)p0 = make_float2(acc[mi][nj][0], acc[mi][nj][1]);
            *(float2*)p1 = make_float2(acc[mi][nj][2], acc[mi][nj][3]);
        }
    }
}

// ---------------------------------------------------------------------------
// Fused RMSNorm + RoPE + hi/lo split (strided QKV input).
// ---------------------------------------------------------------------------
__global__ __launch_bounds__(128) void norm_rope_split(
    const float* __restrict__ src, int srcOff,
    __nv_bfloat16* __restrict__ hi, __nv_bfloat16* __restrict__ lo,
    const float* __restrict__ w,
    const float* __restrict__ cs, const float* __restrict__ sn, int nh)
{
    const int row = blockIdx.x;
    const int m = row / nh, h = row - m * nh;
    const int s = m % S_;
    const int i = threadIdx.x;
    const float* p = src + (size_t)m * NQKV + srcOff + h * HD_;
    float v = p[i];
    float ss = v * v;
#pragma unroll
    for (int o = 16; o; o >>= 1) ss += __shfl_xor_sync(0xffffffff, ss, o);
    __shared__ float wsum[4];
    __shared__ float nbuf[HD_];
    if ((i & 31) == 0) wsum[i >> 5] = ss;
    __syncthreads();
    float tot = wsum[0] + wsum[1] + wsum[2] + wsum[3];
    float rstd = rsqrtf(tot * (1.0f / HD_) + 1e-5f);
    float n = v * rstd * w[i];
    nbuf[i] = n;
    __syncthreads();
    float rot = (i < 64) ? -nbuf[i + 64] : nbuf[i - 64];
    float outv = n * cs[s * HD_ + i] + rot * sn[s * HD_ + i];
    __nv_bfloat16 hb = __float2bfloat16(outv);
    __nv_bfloat16 lb = __float2bfloat16(outv - __bfloat162float(hb));
    hi[(size_t)row * HD_ + i] = hb;
    lo[(size_t)row * HD_ + i] = lb;
}

// ---------------------------------------------------------------------------
// Strided split for V columns of QKV buffer.
// ---------------------------------------------------------------------------
__global__ __launch_bounds__(256) void split_v(const float* __restrict__ src,
                                               __nv_bfloat16* __restrict__ hi,
                                               __nv_bfloat16* __restrict__ lo) {
    int i = blockIdx.x * 256 + threadIdx.x;
    int m = i >> 7, c = i & 127;
    float4 v = *(const float4*)(src + (size_t)m * NQKV + 2560 + c * 4);
    __nv_bfloat16 h0 = __float2bfloat16(v.x), h1 = __float2bfloat16(v.y);
    __nv_bfloat16 h2 = __float2bfloat16(v.z), h3 = __float2bfloat16(v.w);
    __nv_bfloat16 l0 = __float2bfloat16(v.x - __bfloat162float(h0));
    __nv_bfloat16 l1 = __float2bfloat16(v.y - __bfloat162float(h1));
    __nv_bfloat16 l2 = __float2bfloat16(v.z - __bfloat162float(h2));
    __nv_bfloat16 l3 = __float2bfloat16(v.w - __bfloat162float(h3));
    size_t o = (size_t)m * 512 + c * 4;
    __nv_bfloat162* hp = (__nv_bfloat162*)(hi + o);
    __nv_bfloat162* lp = (__nv_bfloat162*)(lo + o);
    hp[0] = __nv_bfloat162(h0, h1); hp[1] = __nv_bfloat162(h2, h3);
    lp[0] = __nv_bfloat162(l0, l1); lp[1] = __nv_bfloat162(l2, l3);
}

// ---------------------------------------------------------------------------
// mma.sync split-bf16 causal GQA flash attention.
// BQ=128, BKV=64, HD=128. 8 warps x 16 q-rows. Double-buffered K/V.
// Term-major MMA ordering; epilogue writes ctx as bf16 hi/lo.
// ---------------------------------------------------------------------------
#define FA_ROWB 272
#define FA_QT  (128 * FA_ROWB)
#define FA_KVT (64 * FA_ROWB)
#define FA_STAGE (4 * FA_KVT)
#define FA_SMEM (2 * FA_QT + 2 * FA_STAGE)

__global__ __launch_bounds__(256, 1) void flash_mma(
    const __nv_bfloat16* __restrict__ qh, const __nv_bfloat16* __restrict__ ql,
    const __nv_bfloat16* __restrict__ kh, const __nv_bfloat16* __restrict__ kl,
    const __nv_bfloat16* __restrict__ vh, const __nv_bfloat16* __restrict__ vl,
    __nv_bfloat16* __restrict__ ch, __nv_bfloat16* __restrict__ cl)
{
    extern __shared__ char sm[];
    const uint32_t sb  = smem_u32(sm);
    const uint32_t sQh = sb, sQl = sb + FA_QT;
    const uint32_t sKV0 = sb + 2 * FA_QT;

    const int b = blockIdx.z, head = blockIdx.y;
    const int qt = gridDim.x - 1 - blockIdx.x;
    const int q0 = qt * 128;
    const int kvh = head / G_;
    const int tid = threadIdx.x, wid = tid >> 5, lane = tid & 31;
    const int m0 = wid * 16;
    const float scale = 0.08838834764831845f;

    {
        const __nv_bfloat16* srcs[2] = { qh, ql };
#pragma unroll
        for (int j = 0; j < 16; j++) {
            int idx = tid + j * 256;
            int t = idx >> 11;
            int e = idx & 2047;
            int r = e >> 4, c = e & 15;
            uint32_t dst = (t ? sQl : sQh) + (uint32_t)(r * FA_ROWB + c * 16);
            cpa16(dst, srcs[t] + ((size_t)(b * S_ + q0 + r) * H_ + head) * HD_ + c * 8);
        }
    }
    auto load_kv = [&](int kt) {
        uint32_t st = sKV0 + (uint32_t)(kt & 1) * FA_STAGE;
        const __nv_bfloat16* srcs[4] = { kh, kl, vh, vl };
#pragma unroll
        for (int j = 0; j < 16; j++) {
            int idx = tid + j * 256;
            int t4 = idx >> 10;
            int e = idx & 1023;
            int r = e >> 4, c = e & 15;
            uint32_t dst = st + (uint32_t)t4 * FA_KVT + (uint32_t)(r * FA_ROWB + c * 16);
            cpa16(dst, srcs[t4] + ((size_t)(b * S_ + kt * 64 + r) * KV_ + kvh) * HD_ + c * 8);
        }
    };
    load_kv(0);
    cpa_commit();

    const uint32_t aoff = (uint32_t)((lane & 15) * FA_ROWB + (lane >> 4) * 16);
    const uint32_t boff = (uint32_t)(((lane & 7) + 8 * (lane >> 4)) * FA_ROWB +
                                     ((lane >> 3) & 1) * 16);

    float oacc[16][4];
#pragma unroll
    for (int nf = 0; nf < 16; nf++)
#pragma unroll
        for (int e = 0; e < 4; e++) oacc[nf][e] = 0.0f;
    float mold[2] = { -1e30f, -1e30f }, lsum[2] = { 0.0f, 0.0f };

    const int nkv = 2 * (qt + 1);
    for (int kt = 0; kt < nkv; kt++) {
        if (kt + 1 < nkv) { load_kv(kt + 1); cpa_commit(); cpa_wait<1>(); }
        else cpa_wait<0>();
        __syncthreads();

        uint32_t st = sKV0 + (uint32_t)(kt & 1) * FA_STAGE;
        uint32_t sKh = st, sKl = st + FA_KVT;
        uint32_t sVh = st + 2 * FA_KVT, sVl = st + 3 * FA_KVT;

        // ---- S = Q K^T (term-major: 8 independent per term) ----
        float sacc[8][4];
#pragma unroll
        for (int nf = 0; nf < 8; nf++)
#pragma unroll
            for (int e = 0; e < 4; e++) sacc[nf][e] = 0.0f;
#pragma unroll
        for (int ks = 0; ks < 8; ks++) {
            uint32_t bh[8][2], bl[8][2];
#pragma unroll
            for (int njp = 0; njp < 4; njp++) {
                uint32_t r4[4];
                uint32_t bo = (uint32_t)(16 * njp * FA_ROWB) + ks * 32 + boff;
                ldsm4(r4, sKh + bo);
                bh[2 * njp][0] = r4[0]; bh[2 * njp][1] = r4[1];
                bh[2 * njp + 1][0] = r4[2]; bh[2 * njp + 1][1] = r4[3];
                ldsm4(r4, sKl + bo);
                bl[2 * njp][0] = r4[0]; bl[2 * njp][1] = r4[1];
                bl[2 * njp + 1][0] = r4[2]; bl[2 * njp + 1][1] = r4[3];
            }
            uint32_t ah[4], al[4];
            uint32_t ao = (uint32_t)(m0 * FA_ROWB) + ks * 32 + aoff;
            ldsm4(ah, sQh + ao);
            ldsm4(al, sQl + ao);
#pragma unroll
            for (int nf = 0; nf < 8; nf++) mma16816(sacc[nf], ah, bh[nf]);
#pragma unroll
            for (int nf = 0; nf < 8; nf++) mma16816(sacc[nf], ah, bl[nf]);
#pragma unroll
            for (int nf = 0; nf < 8; nf++) mma16816(sacc[nf], al, bh[nf]);
        }

        const bool diag = (kt >= 2 * qt);
        float alpha[2];
#pragma unroll
        for (int hh = 0; hh < 2; hh++) {
            int rowg = q0 + m0 + (lane >> 2) + 8 * hh;
            float mx = mold[hh];
#pragma unroll
            for (int nf = 0; nf < 8; nf++)
#pragma unroll
                for (int e = 0; e < 2; e++) {
                    float v = sacc[nf][2 * hh + e] * scale;
                    if (diag) {
                        int colg = kt * 64 + nf * 8 + 2 * (lane & 3) + e;
                        if (colg > rowg) v = -1e30f;
                    }
                    sacc[nf][2 * hh + e] = v;
                    mx = fmaxf(mx, v);
                }
            mx = fmaxf(mx, __shfl_xor_sync(0xffffffffu, mx, 1));
            mx = fmaxf(mx, __shfl_xor_sync(0xffffffffu, mx, 2));
            float al = __expf(mold[hh] - mx);
            float s = 0.0f;
#pragma unroll
            for (int nf = 0; nf < 8; nf++)
#pragma unroll
                for (int e = 0; e < 2; e++) {
                    float p = __expf(sacc[nf][2 * hh + e] - mx);
                    sacc[nf][2 * hh + e] = p;
                    s += p;
                }
            s += __shfl_xor_sync(0xffffffffu, s, 1);
            s += __shfl_xor_sync(0xffffffffu, s, 2);
            mold[hh] = mx;
            lsum[hh] = lsum[hh] * al + s;
            alpha[hh] = al;
        }

        uint32_t aPh[4][4], aPl[4][4];
#pragma unroll
        for (int kc = 0; kc < 4; kc++) {
            split2(sacc[2 * kc][0],     sacc[2 * kc][1],     aPh[kc][0], aPl[kc][0]);
            split2(sacc[2 * kc][2],     sacc[2 * kc][3],     aPh[kc][1], aPl[kc][1]);
            split2(sacc[2 * kc + 1][0], sacc[2 * kc + 1][1], aPh[kc][2], aPl[kc][2]);
            split2(sacc[2 * kc + 1][2], sacc[2 * kc + 1][3], aPh[kc][3], aPl[kc][3]);
        }

#pragma unroll
        for (int nf = 0; nf < 16; nf++) {
            oacc[nf][0] *= alpha[0]; oacc[nf][1] *= alpha[0];
            oacc[nf][2] *= alpha[1]; oacc[nf][3] *= alpha[1];
        }

        // ---- O += P V: dp-pair unroll, term-major (4 independent accs) ----
#pragma unroll
        for (int kc = 0; kc < 4; kc++) {
#pragma unroll
            for (int dq = 0; dq < 4; dq++) {
                uint32_t r4[4];
                uint32_t vo0 = (uint32_t)(kc * 16 * FA_ROWB) + (2 * dq) * 32 + aoff;
                uint32_t bh[4][2], bl[4][2];
                ldsm4t(r4, sVh + vo0);
                bh[0][0] = r4[0]; bh[0][1] = r4[1]; bh[1][0] = r4[2]; bh[1][1] = r4[3];
                ldsm4t(r4, sVh + vo0 + 32);
                bh[2][0] = r4[0]; bh[2][1] = r4[1]; bh[3][0] = r4[2]; bh[3][1] = r4[3];
                ldsm4t(r4, sVl + vo0);
                bl[0][0] = r4[0]; bl[0][1] = r4[1]; bl[1][0] = r4[2]; bl[1][1] = r4[3];
                ldsm4t(r4, sVl + vo0 + 32);
                bl[2][0] = r4[0]; bl[2][1] = r4[1]; bl[3][0] = r4[2]; bl[3][1] = r4[3];
#pragma unroll
                for (int u = 0; u < 4; u++) mma16816(oacc[4 * dq + u], aPh[kc], bh[u]);
#pragma unroll
                for (int u = 0; u < 4; u++) mma16816(oacc[4 * dq + u], aPh[kc], bl[u]);
#pragma unroll
                for (int u = 0; u < 4; u++) mma16816(oacc[4 * dq + u], aPl[kc], bh[u]);
            }
        }
        __syncthreads();
    }

    // ---- epilogue: normalize, split to bf16 hi/lo, store ----
    float linv[2] = { 1.0f / lsum[0], 1.0f / lsum[1] };
#pragma unroll
    for (int nf = 0; nf < 16; nf++) {
#pragma unroll
        for (int hh = 0; hh < 2; hh++) {
            int rq = q0 + m0 + (lane >> 2) + 8 * hh;
            int col = head * HD_ + nf * 8 + 2 * (lane & 3);
            float v0 = oacc[nf][2 * hh] * linv[hh];
            float v1 = oacc[nf][2 * hh + 1] * linv[hh];
            uint32_t hi, lo;
            split2(v0, v1, hi, lo);
            size_t o = (size_t)(b * S_ + rq) * D_ + col;
            *(uint32_t*)(ch + o) = hi;
            *(uint32_t*)(cl + o) = lo;
        }
    }
}

// ---------------------------------------------------------------------------
extern "C" void kernel_launch(void* const* d_in, const int* in_sizes, int n_in,
                              void* d_out, int out_size) {
    const float* x    = (const float*)d_in[0];
    const float* cs   = (const float*)d_in[2];
    const float* sn   = (const float*)d_in[3];
    const float* W_q  = (const float*)d_in[4];
    const float* W_k  = (const float*)d_in[5];
    const float* W_v  = (const float*)d_in[6];
    const float* W_o  = (const float*)d_in[7];
    const float* qnw  = (const float*)d_in[8];
    const float* knw  = (const float*)d_in[9];
    float* out = (float*)d_out;

    float* qkv;
    cudaGetSymbolAddress((void**)&qkv, g_qkv);
    __nv_bfloat16 *xh, *xl, *ch, *cl, *wqkvh, *wqkvl, *woh, *wol;
    __nv_bfloat16 *qhh, *qll, *khh, *kll, *vhh, *vll;
    cudaGetSymbolAddress((void**)&xh,    g_x_hi);    cudaGetSymbolAddress((void**)&xl,    g_x_lo);
    cudaGetSymbolAddress((void**)&ch,    g_ctx_hi);  cudaGetSymbolAddress((void**)&cl,    g_ctx_lo);
    cudaGetSymbolAddress((void**)&wqkvh, g_wqkv_hi); cudaGetSymbolAddress((void**)&wqkvl, g_wqkv_lo);
    cudaGetSymbolAddress((void**)&woh,   g_wo_hi);   cudaGetSymbolAddress((void**)&wol,   g_wo_lo);
    cudaGetSymbolAddress((void**)&qhh,   g_qhi);     cudaGetSymbolAddress((void**)&qll,   g_qlo);
    cudaGetSymbolAddress((void**)&khh,   g_khi);     cudaGetSymbolAddress((void**)&kll,   g_klo);
    cudaGetSymbolAddress((void**)&vhh,   g_vhi);     cudaGetSymbolAddress((void**)&vll,   g_vlo);

    static int attr_set = 0;
    if (!attr_set) {
        cudaFuncSetAttribute(gemm_mma, cudaFuncAttributeMaxDynamicSharedMemorySize, GT_SMEM);
        cudaFuncSetAttribute(flash_mma, cudaFuncAttributeMaxDynamicSharedMemorySize, FA_SMEM);
        attr_set = 1;
    }

    const int M = B_ * S_;              // 4096
    const int NXY = M * D_ / 4;
    const int NW  = D_ * D_ / 4;
    const int NKW = KV_ * HD_ * D_ / 4;

    split_bf16<<<(NXY + 255) / 256, 256>>>(x,   xh,  xl,  NXY);
    split_bf16<<<(NW  + 255) / 256, 256>>>(W_q, wqkvh,                           wqkvl,                           NW);
    split_bf16<<<(NKW + 255) / 256, 256>>>(W_k, wqkvh + (size_t)D_ * D_,         wqkvl + (size_t)D_ * D_,         NKW);
    split_bf16<<<(NKW + 255) / 256, 256>>>(W_v, wqkvh + (size_t)(D_ + 512) * D_, wqkvl + (size_t)(D_ + 512) * D_, NKW);
    split_bf16<<<(NW  + 255) / 256, 256>>>(W_o, woh, wol, NW);

    // Fused QKV projection
    {
        dim3 g(NQKV / 128, M / 128);
        gemm_mma<<<g, 256, GT_SMEM>>>(xh, xl, wqkvh, wqkvl, qkv, M, NQKV, D_);
    }

    // RMSNorm + RoPE + split (q, k); plain split (v)
    norm_rope_split<<<M * H_, 128>>>(qkv, 0,    qhh, qll, qnw, cs, sn, H_);
    norm_rope_split<<<M * KV_, 128>>>(qkv, 2048, khh, kll, knw, cs, sn, KV_);
    split_v<<<M * 128 / 256, 256>>>(qkv, vhh, vll);

    // Attention
    {
        dim3 g(S_ / 128, H_, B_);
        flash_mma<<<g, 256, FA_SMEM>>>(qhh, qll, khh, kll, vhh, vll, ch, cl);
    }

    // Output projection
    {
        dim3 go(D_ / 128, M / 128);
        gemm_mma<<<go, 256, GT_SMEM>>>(ch, cl, woh, wol, out, M, D_, D_);
    }
}

// round 16
// speedup vs baseline: 3.9860x; 1.1020x over previous
#include <cuda_runtime.h>
#include <cuda_bf16.h>
#include <math.h>
#include <stdint.h>

#define B_  2
#define S_  2048
#define D_  2048
#define H_  16
#define KV_ 4
#define HD_ 128
#define G_  4
#define NQKV 3072                    // 2048 q + 512 k + 512 v

// ---------------- scratch (static device globals; no allocation allowed) ----
__device__ float g_qkv[(size_t)B_*S_*NQKV];                  // fused QKV fp32
__device__ __nv_bfloat16 g_x_hi[(size_t)B_*S_*D_],    g_x_lo[(size_t)B_*S_*D_];
__device__ __nv_bfloat16 g_ctx_hi[(size_t)B_*S_*D_],  g_ctx_lo[(size_t)B_*S_*D_];
__device__ __nv_bfloat16 g_wqkv_hi[(size_t)NQKV*D_],  g_wqkv_lo[(size_t)NQKV*D_];
__device__ __nv_bfloat16 g_wo_hi[(size_t)D_*D_],      g_wo_lo[(size_t)D_*D_];
// attention hi/lo buffers
__device__ __nv_bfloat16 g_qhi[(size_t)B_*S_*H_*HD_],  g_qlo[(size_t)B_*S_*H_*HD_];
__device__ __nv_bfloat16 g_khi[(size_t)B_*S_*KV_*HD_], g_klo[(size_t)B_*S_*KV_*HD_];
__device__ __nv_bfloat16 g_vhi[(size_t)B_*S_*KV_*HD_], g_vlo[(size_t)B_*S_*KV_*HD_];

// ---------------- ptx helpers (plain compute_103-safe only) -----------------
__device__ __forceinline__ uint32_t smem_u32(const void* p) {
    uint32_t a;
    asm("{ .reg .u64 t; cvta.to.shared.u64 t, %1; cvt.u32.u64 %0, t; }"
        : "=r"(a) : "l"(p));
    return a;
}
__device__ __forceinline__ void cpa16(uint32_t s, const void* g) {
    asm volatile("cp.async.cg.shared.global [%0], [%1], 16;"
                 :: "r"(s), "l"(g) : "memory");
}
__device__ __forceinline__ void cpa_commit() {
    asm volatile("cp.async.commit_group;" ::: "memory");
}
template<int N> __device__ __forceinline__ void cpa_wait() {
    asm volatile("cp.async.wait_group %0;" :: "n"(N) : "memory");
}
__device__ __forceinline__ void ldsm4(uint32_t* r, uint32_t addr) {
    asm volatile("ldmatrix.sync.aligned.m8n8.x4.shared.b16 {%0,%1,%2,%3}, [%4];"
                 : "=r"(r[0]), "=r"(r[1]), "=r"(r[2]), "=r"(r[3]) : "r"(addr));
}
__device__ __forceinline__ void ldsm4t(uint32_t* r, uint32_t addr) {
    asm volatile("ldmatrix.sync.aligned.m8n8.x4.trans.shared.b16 {%0,%1,%2,%3}, [%4];"
                 : "=r"(r[0]), "=r"(r[1]), "=r"(r[2]), "=r"(r[3]) : "r"(addr));
}
__device__ __forceinline__ void mma16816(float* c, const uint32_t* a, const uint32_t* b) {
    asm volatile(
        "mma.sync.aligned.m16n8k16.row.col.f32.bf16.bf16.f32 "
        "{%0,%1,%2,%3}, {%4,%5,%6,%7}, {%8,%9}, {%0,%1,%2,%3};"
        : "+f"(c[0]), "+f"(c[1]), "+f"(c[2]), "+f"(c[3])
        : "r"(a[0]), "r"(a[1]), "r"(a[2]), "r"(a[3]), "r"(b[0]), "r"(b[1]));
}
__device__ __forceinline__ void split2(float a, float b, uint32_t& hi, uint32_t& lo) {
    __nv_bfloat162 h = __floats2bfloat162_rn(a, b);
    hi = *(uint32_t*)&h;
    float ra = a - __bfloat162float(h.x);
    float rb = b - __bfloat162float(h.y);
    __nv_bfloat162 l = __floats2bfloat162_rn(ra, rb);
    lo = *(uint32_t*)&l;
}

// ---------------------------------------------------------------------------
// split fp32 -> (hi, lo) bf16 (contiguous)
// ---------------------------------------------------------------------------
__global__ __launch_bounds__(256) void split_bf16(const float* __restrict__ s,
                                                  __nv_bfloat16* __restrict__ hi,
                                                  __nv_bfloat16* __restrict__ lo,
                                                  int n4) {
    int i = blockIdx.x * 256 + threadIdx.x;
    if (i >= n4) return;
    float4 v = ((const float4*)s)[i];
    __nv_bfloat16 h0 = __float2bfloat16(v.x), h1 = __float2bfloat16(v.y);
    __nv_bfloat16 h2 = __float2bfloat16(v.z), h3 = __float2bfloat16(v.w);
    __nv_bfloat16 l0 = __float2bfloat16(v.x - __bfloat162float(h0));
    __nv_bfloat16 l1 = __float2bfloat16(v.y - __bfloat162float(h1));
    __nv_bfloat16 l2 = __float2bfloat16(v.z - __bfloat162float(h2));
    __nv_bfloat16 l3 = __float2bfloat16(v.w - __bfloat162float(h3));
    __nv_bfloat162* hp = (__nv_bfloat162*)(hi + (size_t)i * 4);
    __nv_bfloat162* lp = (__nv_bfloat162*)(lo + (size_t)i * 4);
    hp[0] = __nv_bfloat162(h0, h1); hp[1] = __nv_bfloat162(h2, h3);
    lp[0] = __nv_bfloat162(l0, l1); lp[1] = __nv_bfloat162(l2, l3);
}

// ---------------------------------------------------------------------------
// mma.sync split-bf16 GEMM.
// 128x128 tile, BK=32, 2-stage cp.async pipeline, 2 CTAs/SM (80 KB smem,
// <=128 regs), 8 warps (2m x 4n), warp tile 64x32, term-major MMA order.
// Cross-CTA overlap hides barrier/load stalls.
// ---------------------------------------------------------------------------
#define BKC 32
#define TILEB (128 * 40 * 2)
#define STAGEB (4 * TILEB)
#define STAGES 2
#define GT_SMEM (STAGES * STAGEB)          // 81920 B

__global__ __launch_bounds__(256, 2) void gemm_mma(
    const __nv_bfloat16* __restrict__ Ahi, const __nv_bfloat16* __restrict__ Alo,
    const __nv_bfloat16* __restrict__ Bhi, const __nv_bfloat16* __restrict__ Blo,
    float* __restrict__ C, int M, int N, int K)
{
    extern __shared__ char sm[];
    const uint32_t sb = smem_u32(sm);
    const int tid = threadIdx.x;
    const int wid = tid >> 5, lane = tid & 31;
    const int wm = (wid >> 2) * 64;
    const int wn = (wid & 3) * 32;
    const int rowBase = blockIdx.y * 128;
    const int colBase = blockIdx.x * 128;
    const int NC = K / BKC;

    const __nv_bfloat16* srcs[4] = {
        Ahi + (size_t)rowBase * K, Alo + (size_t)rowBase * K,
        Bhi + (size_t)colBase * K, Blo + (size_t)colBase * K };

    auto load_chunk = [&](int c) {
        uint32_t stb = sb + (uint32_t)(c & (STAGES - 1)) * STAGEB;
#pragma unroll
        for (int j = 0; j < 8; j++) {
            int idx = tid + j * 256;
            int t4 = idx >> 9;
            int e  = idx & 511;
            int r  = e >> 2, c4 = e & 3;
            uint32_t dst = stb + (uint32_t)t4 * TILEB + (uint32_t)(r * 80 + c4 * 16);
            cpa16(dst, srcs[t4] + (size_t)c * BKC + (size_t)r * K + c4 * 8);
        }
        cpa_commit();
    };

    const uint32_t aoff = (uint32_t)((lane & 15) * 80 + (lane >> 4) * 16);
    const uint32_t boff = (uint32_t)(((lane & 7) + 8 * (lane >> 4)) * 80 +
                                     ((lane >> 3) & 1) * 16);

    float acc[4][4][4];
#pragma unroll
    for (int mi = 0; mi < 4; mi++)
#pragma unroll
        for (int nj = 0; nj < 4; nj++)
#pragma unroll
            for (int e = 0; e < 4; e++) acc[mi][nj][e] = 0.0f;

    load_chunk(0);
    load_chunk(1);

    for (int c = 0; c < NC; c++) {
        cpa_wait<1>();                    // chunk c landed (this thread)
        __syncthreads();                  // visible to all warps

        uint32_t stb = sb + (uint32_t)(c & (STAGES - 1)) * STAGEB;
        const uint32_t sAhi = stb, sAlo = stb + TILEB;
        const uint32_t sBhi = stb + 2 * TILEB, sBlo = stb + 3 * TILEB;

#pragma unroll
        for (int ks = 0; ks < 2; ks++) {
            uint32_t kb = (uint32_t)(32 * ks);
            uint32_t bhi[4][2], blo[4][2];
#pragma unroll
            for (int njp = 0; njp < 2; njp++) {
                uint32_t r4[4];
                uint32_t bo = (uint32_t)((wn + 16 * njp) * 80) + kb + boff;
                ldsm4(r4, sBhi + bo);
                bhi[2 * njp][0] = r4[0]; bhi[2 * njp][1] = r4[1];
                bhi[2 * njp + 1][0] = r4[2]; bhi[2 * njp + 1][1] = r4[3];
                ldsm4(r4, sBlo + bo);
                blo[2 * njp][0] = r4[0]; blo[2 * njp][1] = r4[1];
                blo[2 * njp + 1][0] = r4[2]; blo[2 * njp + 1][1] = r4[3];
            }
            uint32_t ahi[4][4], alo[4][4];
#pragma unroll
            for (int mi = 0; mi < 4; mi++) {
                uint32_t ao = (uint32_t)((wm + 16 * mi) * 80) + kb + aoff;
                ldsm4(ahi[mi], sAhi + ao);
                ldsm4(alo[mi], sAlo + ao);
            }
#pragma unroll
            for (int mi = 0; mi < 4; mi++)
#pragma unroll
                for (int nj = 0; nj < 4; nj++)
                    mma16816(acc[mi][nj], ahi[mi], bhi[nj]);
#pragma unroll
            for (int mi = 0; mi < 4; mi++)
#pragma unroll
                for (int nj = 0; nj < 4; nj++)
                    mma16816(acc[mi][nj], ahi[mi], blo[nj]);
#pragma unroll
            for (int mi = 0; mi < 4; mi++)
#pragma unroll
                for (int nj = 0; nj < 4; nj++)
                    mma16816(acc[mi][nj], alo[mi], bhi[nj]);
        }
        __syncthreads();                  // all warps done reading slot c%2
        if (c + 2 < NC) load_chunk(c + 2);
        else cpa_commit();                // keep group accounting aligned
    }

    const int r0 = rowBase + wm + (lane >> 2);
    const int c0 = colBase + wn + 2 * (lane & 3);
#pragma unroll
    for (int mi = 0; mi < 4; mi++) {
#pragma unroll
        for (int nj = 0; nj < 4; nj++) {
            float* p0 = C + (size_t)(r0 + 16 * mi) * N + c0 + 8 * nj;
            float* p1 = p0 + (size_t)8 * N;
            *(float2*)p0 = make_float2(acc[mi][nj][0], acc[mi][nj][1]);
            *(float2*)p1 = make_float2(acc[mi][nj][2], acc[mi][nj][3]);
        }
    }
}

// ---------------------------------------------------------------------------
// Fused RMSNorm + RoPE + hi/lo split (strided QKV input).
// ---------------------------------------------------------------------------
__global__ __launch_bounds__(128) void norm_rope_split(
    const float* __restrict__ src, int srcOff,
    __nv_bfloat16* __restrict__ hi, __nv_bfloat16* __restrict__ lo,
    const float* __restrict__ w,
    const float* __restrict__ cs, const float* __restrict__ sn, int nh)
{
    const int row = blockIdx.x;
    const int m = row / nh, h = row - m * nh;
    const int s = m % S_;
    const int i = threadIdx.x;
    const float* p = src + (size_t)m * NQKV + srcOff + h * HD_;
    float v = p[i];
    float ss = v * v;
#pragma unroll
    for (int o = 16; o; o >>= 1) ss += __shfl_xor_sync(0xffffffff, ss, o);
    __shared__ float wsum[4];
    __shared__ float nbuf[HD_];
    if ((i & 31) == 0) wsum[i >> 5] = ss;
    __syncthreads();
    float tot = wsum[0] + wsum[1] + wsum[2] + wsum[3];
    float rstd = rsqrtf(tot * (1.0f / HD_) + 1e-5f);
    float n = v * rstd * w[i];
    nbuf[i] = n;
    __syncthreads();
    float rot = (i < 64) ? -nbuf[i + 64] : nbuf[i - 64];
    float outv = n * cs[s * HD_ + i] + rot * sn[s * HD_ + i];
    __nv_bfloat16 hb = __float2bfloat16(outv);
    __nv_bfloat16 lb = __float2bfloat16(outv - __bfloat162float(hb));
    hi[(size_t)row * HD_ + i] = hb;
    lo[(size_t)row * HD_ + i] = lb;
}

// ---------------------------------------------------------------------------
// Strided split for V columns of QKV buffer.
// ---------------------------------------------------------------------------
__global__ __launch_bounds__(256) void split_v(const float* __restrict__ src,
                                               __nv_bfloat16* __restrict__ hi,
                                               __nv_bfloat16* __restrict__ lo) {
    int i = blockIdx.x * 256 + threadIdx.x;
    int m = i >> 7, c = i & 127;
    float4 v = *(const float4*)(src + (size_t)m * NQKV + 2560 + c * 4);
    __nv_bfloat16 h0 = __float2bfloat16(v.x), h1 = __float2bfloat16(v.y);
    __nv_bfloat16 h2 = __float2bfloat16(v.z), h3 = __float2bfloat16(v.w);
    __nv_bfloat16 l0 = __float2bfloat16(v.x - __bfloat162float(h0));
    __nv_bfloat16 l1 = __float2bfloat16(v.y - __bfloat162float(h1));
    __nv_bfloat16 l2 = __float2bfloat16(v.z - __bfloat162float(h2));
    __nv_bfloat16 l3 = __float2bfloat16(v.w - __bfloat162float(h3));
    size_t o = (size_t)m * 512 + c * 4;
    __nv_bfloat162* hp = (__nv_bfloat162*)(hi + o);
    __nv_bfloat162* lp = (__nv_bfloat162*)(lo + o);
    hp[0] = __nv_bfloat162(h0, h1); hp[1] = __nv_bfloat162(h2, h3);
    lp[0] = __nv_bfloat162(l0, l1); lp[1] = __nv_bfloat162(l2, l3);
}

// ---------------------------------------------------------------------------
// mma.sync split-bf16 causal GQA flash attention (unchanged).
// BQ=128, BKV=64, HD=128. 8 warps x 16 q-rows. Double-buffered K/V.
// ---------------------------------------------------------------------------
#define FA_ROWB 272
#define FA_QT  (128 * FA_ROWB)
#define FA_KVT (64 * FA_ROWB)
#define FA_STAGE (4 * FA_KVT)
#define FA_SMEM (2 * FA_QT + 2 * FA_STAGE)

__global__ __launch_bounds__(256, 1) void flash_mma(
    const __nv_bfloat16* __restrict__ qh, const __nv_bfloat16* __restrict__ ql,
    const __nv_bfloat16* __restrict__ kh, const __nv_bfloat16* __restrict__ kl,
    const __nv_bfloat16* __restrict__ vh, const __nv_bfloat16* __restrict__ vl,
    __nv_bfloat16* __restrict__ ch, __nv_bfloat16* __restrict__ cl)
{
    extern __shared__ char sm[];
    const uint32_t sb  = smem_u32(sm);
    const uint32_t sQh = sb, sQl = sb + FA_QT;
    const uint32_t sKV0 = sb + 2 * FA_QT;

    const int b = blockIdx.z, head = blockIdx.y;
    const int qt = gridDim.x - 1 - blockIdx.x;
    const int q0 = qt * 128;
    const int kvh = head / G_;
    const int tid = threadIdx.x, wid = tid >> 5, lane = tid & 31;
    const int m0 = wid * 16;
    const float scale = 0.08838834764831845f;

    {
        const __nv_bfloat16* srcs[2] = { qh, ql };
#pragma unroll
        for (int j = 0; j < 16; j++) {
            int idx = tid + j * 256;
            int t = idx >> 11;
            int e = idx & 2047;
            int r = e >> 4, c = e & 15;
            uint32_t dst = (t ? sQl : sQh) + (uint32_t)(r * FA_ROWB + c * 16);
            cpa16(dst, srcs[t] + ((size_t)(b * S_ + q0 + r) * H_ + head) * HD_ + c * 8);
        }
    }
    auto load_kv = [&](int kt) {
        uint32_t st = sKV0 + (uint32_t)(kt & 1) * FA_STAGE;
        const __nv_bfloat16* srcs[4] = { kh, kl, vh, vl };
#pragma unroll
        for (int j = 0; j < 16; j++) {
            int idx = tid + j * 256;
            int t4 = idx >> 10;
            int e = idx & 1023;
            int r = e >> 4, c = e & 15;
            uint32_t dst = st + (uint32_t)t4 * FA_KVT + (uint32_t)(r * FA_ROWB + c * 16);
            cpa16(dst, srcs[t4] + ((size_t)(b * S_ + kt * 64 + r) * KV_ + kvh) * HD_ + c * 8);
        }
    };
    load_kv(0);
    cpa_commit();

    const uint32_t aoff = (uint32_t)((lane & 15) * FA_ROWB + (lane >> 4) * 16);
    const uint32_t boff = (uint32_t)(((lane & 7) + 8 * (lane >> 4)) * FA_ROWB +
                                     ((lane >> 3) & 1) * 16);

    float oacc[16][4];
#pragma unroll
    for (int nf = 0; nf < 16; nf++)
#pragma unroll
        for (int e = 0; e < 4; e++) oacc[nf][e] = 0.0f;
    float mold[2] = { -1e30f, -1e30f }, lsum[2] = { 0.0f, 0.0f };

    const int nkv = 2 * (qt + 1);
    for (int kt = 0; kt < nkv; kt++) {
        if (kt + 1 < nkv) { load_kv(kt + 1); cpa_commit(); cpa_wait<1>(); }
        else cpa_wait<0>();
        __syncthreads();

        uint32_t st = sKV0 + (uint32_t)(kt & 1) * FA_STAGE;
        uint32_t sKh = st, sKl = st + FA_KVT;
        uint32_t sVh = st + 2 * FA_KVT, sVl = st + 3 * FA_KVT;

        float sacc[8][4];
#pragma unroll
        for (int nf = 0; nf < 8; nf++)
#pragma unroll
            for (int e = 0; e < 4; e++) sacc[nf][e] = 0.0f;
#pragma unroll
        for (int ks = 0; ks < 8; ks++) {
            uint32_t bh[8][2], bl[8][2];
#pragma unroll
            for (int njp = 0; njp < 4; njp++) {
                uint32_t r4[4];
                uint32_t bo = (uint32_t)(16 * njp * FA_ROWB) + ks * 32 + boff;
                ldsm4(r4, sKh + bo);
                bh[2 * njp][0] = r4[0]; bh[2 * njp][1] = r4[1];
                bh[2 * njp + 1][0] = r4[2]; bh[2 * njp + 1][1] = r4[3];
                ldsm4(r4, sKl + bo);
                bl[2 * njp][0] = r4[0]; bl[2 * njp][1] = r4[1];
                bl[2 * njp + 1][0] = r4[2]; bl[2 * njp + 1][1] = r4[3];
            }
            uint32_t ah[4], al[4];
            uint32_t ao = (uint32_t)(m0 * FA_ROWB) + ks * 32 + aoff;
            ldsm4(ah, sQh + ao);
            ldsm4(al, sQl + ao);
#pragma unroll
            for (int nf = 0; nf < 8; nf++) mma16816(sacc[nf], ah, bh[nf]);
#pragma unroll
            for (int nf = 0; nf < 8; nf++) mma16816(sacc[nf], ah, bl[nf]);
#pragma unroll
            for (int nf = 0; nf < 8; nf++) mma16816(sacc[nf], al, bh[nf]);
        }

        const bool diag = (kt >= 2 * qt);
        float alpha[2];
#pragma unroll
        for (int hh = 0; hh < 2; hh++) {
            int rowg = q0 + m0 + (lane >> 2) + 8 * hh;
            float mx = mold[hh];
#pragma unroll
            for (int nf = 0; nf < 8; nf++)
#pragma unroll
                for (int e = 0; e < 2; e++) {
                    float v = sacc[nf][2 * hh + e] * scale;
                    if (diag) {
                        int colg = kt * 64 + nf * 8 + 2 * (lane & 3) + e;
                        if (colg > rowg) v = -1e30f;
                    }
                    sacc[nf][2 * hh + e] = v;
                    mx = fmaxf(mx, v);
                }
            mx = fmaxf(mx, __shfl_xor_sync(0xffffffffu, mx, 1));
            mx = fmaxf(mx, __shfl_xor_sync(0xffffffffu, mx, 2));
            float al = __expf(mold[hh] - mx);
            float s = 0.0f;
#pragma unroll
            for (int nf = 0; nf < 8; nf++)
#pragma unroll
                for (int e = 0; e < 2; e++) {
                    float p = __expf(sacc[nf][2 * hh + e] - mx);
                    sacc[nf][2 * hh + e] = p;
                    s += p;
                }
            s += __shfl_xor_sync(0xffffffffu, s, 1);
            s += __shfl_xor_sync(0xffffffffu, s, 2);
            mold[hh] = mx;
            lsum[hh] = lsum[hh] * al + s;
            alpha[hh] = al;
        }

        uint32_t aPh[4][4], aPl[4][4];
#pragma unroll
        for (int kc = 0; kc < 4; kc++) {
            split2(sacc[2 * kc][0],     sacc[2 * kc][1],     aPh[kc][0], aPl[kc][0]);
            split2(sacc[2 * kc][2],     sacc[2 * kc][3],     aPh[kc][1], aPl[kc][1]);
            split2(sacc[2 * kc + 1][0], sacc[2 * kc + 1][1], aPh[kc][2], aPl[kc][2]);
            split2(sacc[2 * kc + 1][2], sacc[2 * kc + 1][3], aPh[kc][3], aPl[kc][3]);
        }

#pragma unroll
        for (int nf = 0; nf < 16; nf++) {
            oacc[nf][0] *= alpha[0]; oacc[nf][1] *= alpha[0];
            oacc[nf][2] *= alpha[1]; oacc[nf][3] *= alpha[1];
        }

#pragma unroll
        for (int kc = 0; kc < 4; kc++) {
#pragma unroll
            for (int dq = 0; dq < 4; dq++) {
                uint32_t r4[4];
                uint32_t vo0 = (uint32_t)(kc * 16 * FA_ROWB) + (2 * dq) * 32 + aoff;
                uint32_t bh[4][2], bl[4][2];
                ldsm4t(r4, sVh + vo0);
                bh[0][0] = r4[0]; bh[0][1] = r4[1]; bh[1][0] = r4[2]; bh[1][1] = r4[3];
                ldsm4t(r4, sVh + vo0 + 32);
                bh[2][0] = r4[0]; bh[2][1] = r4[1]; bh[3][0] = r4[2]; bh[3][1] = r4[3];
                ldsm4t(r4, sVl + vo0);
                bl[0][0] = r4[0]; bl[0][1] = r4[1]; bl[1][0] = r4[2]; bl[1][1] = r4[3];
                ldsm4t(r4, sVl + vo0 + 32);
                bl[2][0] = r4[0]; bl[2][1] = r4[1]; bl[3][0] = r4[2]; bl[3][1] = r4[3];
#pragma unroll
                for (int u = 0; u < 4; u++) mma16816(oacc[4 * dq + u], aPh[kc], bh[u]);
#pragma unroll
                for (int u = 0; u < 4; u++) mma16816(oacc[4 * dq + u], aPh[kc], bl[u]);
#pragma unroll
                for (int u = 0; u < 4; u++) mma16816(oacc[4 * dq + u], aPl[kc], bh[u]);
            }
        }
        __syncthreads();
    }

    float linv[2] = { 1.0f / lsum[0], 1.0f / lsum[1] };
#pragma unroll
    for (int nf = 0; nf < 16; nf++) {
#pragma unroll
        for (int hh = 0; hh < 2; hh++) {
            int rq = q0 + m0 + (lane >> 2) + 8 * hh;
            int col = head * HD_ + nf * 8 + 2 * (lane & 3);
            float v0 = oacc[nf][2 * hh] * linv[hh];
            float v1 = oacc[nf][2 * hh + 1] * linv[hh];
            uint32_t hi, lo;
            split2(v0, v1, hi, lo);
            size_t o = (size_t)(b * S_ + rq) * D_ + col;
            *(uint32_t*)(ch + o) = hi;
            *(uint32_t*)(cl + o) = lo;
        }
    }
}

// ---------------------------------------------------------------------------
extern "C" void kernel_launch(void* const* d_in, const int* in_sizes, int n_in,
                              void* d_out, int out_size) {
    const float* x    = (const float*)d_in[0];
    const float* cs   = (const float*)d_in[2];
    const float* sn   = (const float*)d_in[3];
    const float* W_q  = (const float*)d_in[4];
    const float* W_k  = (const float*)d_in[5];
    const float* W_v  = (const float*)d_in[6];
    const float* W_o  = (const float*)d_in[7];
    const float* qnw  = (const float*)d_in[8];
    const float* knw  = (const float*)d_in[9];
    float* out = (float*)d_out;

    float* qkv;
    cudaGetSymbolAddress((void**)&qkv, g_qkv);
    __nv_bfloat16 *xh, *xl, *ch, *cl, *wqkvh, *wqkvl, *woh, *wol;
    __nv_bfloat16 *qhh, *qll, *khh, *kll, *vhh, *vll;
    cudaGetSymbolAddress((void**)&xh,    g_x_hi);    cudaGetSymbolAddress((void**)&xl,    g_x_lo);
    cudaGetSymbolAddress((void**)&ch,    g_ctx_hi);  cudaGetSymbolAddress((void**)&cl,    g_ctx_lo);
    cudaGetSymbolAddress((void**)&wqkvh, g_wqkv_hi); cudaGetSymbolAddress((void**)&wqkvl, g_wqkv_lo);
    cudaGetSymbolAddress((void**)&woh,   g_wo_hi);   cudaGetSymbolAddress((void**)&wol,   g_wo_lo);
    cudaGetSymbolAddress((void**)&qhh,   g_qhi);     cudaGetSymbolAddress((void**)&qll,   g_qlo);
    cudaGetSymbolAddress((void**)&khh,   g_khi);     cudaGetSymbolAddress((void**)&kll,   g_klo);
    cudaGetSymbolAddress((void**)&vhh,   g_vhi);     cudaGetSymbolAddress((void**)&vll,   g_vlo);

    static int attr_set = 0;
    if (!attr_set) {
        cudaFuncSetAttribute(gemm_mma, cudaFuncAttributeMaxDynamicSharedMemorySize, GT_SMEM);
        cudaFuncSetAttribute(flash_mma, cudaFuncAttributeMaxDynamicSharedMemorySize, FA_SMEM);
        attr_set = 1;
    }

    const int M = B_ * S_;              // 4096
    const int NXY = M * D_ / 4;
    const int NW  = D_ * D_ / 4;
    const int NKW = KV_ * HD_ * D_ / 4;

    split_bf16<<<(NXY + 255) / 256, 256>>>(x,   xh,  xl,  NXY);
    split_bf16<<<(NW  + 255) / 256, 256>>>(W_q, wqkvh,                           wqkvl,                           NW);
    split_bf16<<<(NKW + 255) / 256, 256>>>(W_k, wqkvh + (size_t)D_ * D_,         wqkvl + (size_t)D_ * D_,         NKW);
    split_bf16<<<(NKW + 255) / 256, 256>>>(W_v, wqkvh + (size_t)(D_ + 512) * D_, wqkvl + (size_t)(D_ + 512) * D_, NKW);
    split_bf16<<<(NW  + 255) / 256, 256>>>(W_o, woh, wol, NW);

    // Fused QKV projection
    {
        dim3 g(NQKV / 128, M / 128);
        gemm_mma<<<g, 256, GT_SMEM>>>(xh, xl, wqkvh, wqkvl, qkv, M, NQKV, D_);
    }

    // RMSNorm + RoPE + split (q, k); plain split (v)
    norm_rope_split<<<M * H_, 128>>>(qkv, 0,    qhh, qll, qnw, cs, sn, H_);
    norm_rope_split<<<M * KV_, 128>>>(qkv, 2048, khh, kll, knw, cs, sn, KV_);
    split_v<<<M * 128 / 256, 256>>>(qkv, vhh, vll);

    // Attention
    {
        dim3 g(S_ / 128, H_, B_);
        flash_mma<<<g, 256, FA_SMEM>>>(qhh, qll, khh, kll, vhh, vll, ch, cl);
    }

    // Output projection
    {
        dim3 go(D_ / 128, M / 128);
        gemm_mma<<<go, 256, GT_SMEM>>>(ch, cl, woh, wol, out, M, D_, D_);
    }
}

// round 17
// speedup vs baseline: 4.0145x; 1.0072x over previous
#include <cuda_runtime.h>
#include <cuda_bf16.h>
#include <math.h>
#include <stdint.h>

#define B_  2
#define S_  2048
#define D_  2048
#define H_  16
#define KV_ 4
#define HD_ 128
#define G_  4
#define NQKV 3072                    // 2048 q + 512 k + 512 v

// ---------------- scratch (static device globals; no allocation allowed) ----
__device__ float g_qkv[(size_t)B_*S_*NQKV];                  // fused QKV fp32
__device__ __nv_bfloat16 g_x_hi[(size_t)B_*S_*D_],    g_x_lo[(size_t)B_*S_*D_];
__device__ __nv_bfloat16 g_ctx_hi[(size_t)B_*S_*D_],  g_ctx_lo[(size_t)B_*S_*D_];
__device__ __nv_bfloat16 g_wqkv_hi[(size_t)NQKV*D_],  g_wqkv_lo[(size_t)NQKV*D_];
__device__ __nv_bfloat16 g_wo_hi[(size_t)D_*D_],      g_wo_lo[(size_t)D_*D_];
// attention hi/lo buffers
__device__ __nv_bfloat16 g_qhi[(size_t)B_*S_*H_*HD_],  g_qlo[(size_t)B_*S_*H_*HD_];
__device__ __nv_bfloat16 g_khi[(size_t)B_*S_*KV_*HD_], g_klo[(size_t)B_*S_*KV_*HD_];
__device__ __nv_bfloat16 g_vhi[(size_t)B_*S_*KV_*HD_], g_vlo[(size_t)B_*S_*KV_*HD_];

// ---------------- ptx helpers (plain compute_103-safe only) -----------------
__device__ __forceinline__ uint32_t smem_u32(const void* p) {
    uint32_t a;
    asm("{ .reg .u64 t; cvta.to.shared.u64 t, %1; cvt.u32.u64 %0, t; }"
        : "=r"(a) : "l"(p));
    return a;
}
__device__ __forceinline__ void cpa16(uint32_t s, const void* g) {
    asm volatile("cp.async.cg.shared.global [%0], [%1], 16;"
                 :: "r"(s), "l"(g) : "memory");
}
__device__ __forceinline__ void cpa_commit() {
    asm volatile("cp.async.commit_group;" ::: "memory");
}
template<int N> __device__ __forceinline__ void cpa_wait() {
    asm volatile("cp.async.wait_group %0;" :: "n"(N) : "memory");
}
__device__ __forceinline__ void ldsm4(uint32_t* r, uint32_t addr) {
    asm volatile("ldmatrix.sync.aligned.m8n8.x4.shared.b16 {%0,%1,%2,%3}, [%4];"
                 : "=r"(r[0]), "=r"(r[1]), "=r"(r[2]), "=r"(r[3]) : "r"(addr));
}
__device__ __forceinline__ void ldsm4t(uint32_t* r, uint32_t addr) {
    asm volatile("ldmatrix.sync.aligned.m8n8.x4.trans.shared.b16 {%0,%1,%2,%3}, [%4];"
                 : "=r"(r[0]), "=r"(r[1]), "=r"(r[2]), "=r"(r[3]) : "r"(addr));
}
__device__ __forceinline__ void mma16816(float* c, const uint32_t* a, const uint32_t* b) {
    asm volatile(
        "mma.sync.aligned.m16n8k16.row.col.f32.bf16.bf16.f32 "
        "{%0,%1,%2,%3}, {%4,%5,%6,%7}, {%8,%9}, {%0,%1,%2,%3};"
        : "+f"(c[0]), "+f"(c[1]), "+f"(c[2]), "+f"(c[3])
        : "r"(a[0]), "r"(a[1]), "r"(a[2]), "r"(a[3]), "r"(b[0]), "r"(b[1]));
}
__device__ __forceinline__ void split2(float a, float b, uint32_t& hi, uint32_t& lo) {
    __nv_bfloat162 h = __floats2bfloat162_rn(a, b);
    hi = *(uint32_t*)&h;
    float ra = a - __bfloat162float(h.x);
    float rb = b - __bfloat162float(h.y);
    __nv_bfloat162 l = __floats2bfloat162_rn(ra, rb);
    lo = *(uint32_t*)&l;
}

// ---------------------------------------------------------------------------
// split fp32 -> (hi, lo) bf16 (contiguous)
// ---------------------------------------------------------------------------
__global__ __launch_bounds__(256) void split_bf16(const float* __restrict__ s,
                                                  __nv_bfloat16* __restrict__ hi,
                                                  __nv_bfloat16* __restrict__ lo,
                                                  int n4) {
    int i = blockIdx.x * 256 + threadIdx.x;
    if (i >= n4) return;
    float4 v = ((const float4*)s)[i];
    __nv_bfloat16 h0 = __float2bfloat16(v.x), h1 = __float2bfloat16(v.y);
    __nv_bfloat16 h2 = __float2bfloat16(v.z), h3 = __float2bfloat16(v.w);
    __nv_bfloat16 l0 = __float2bfloat16(v.x - __bfloat162float(h0));
    __nv_bfloat16 l1 = __float2bfloat16(v.y - __bfloat162float(h1));
    __nv_bfloat16 l2 = __float2bfloat16(v.z - __bfloat162float(h2));
    __nv_bfloat16 l3 = __float2bfloat16(v.w - __bfloat162float(h3));
    __nv_bfloat162* hp = (__nv_bfloat162*)(hi + (size_t)i * 4);
    __nv_bfloat162* lp = (__nv_bfloat162*)(lo + (size_t)i * 4);
    hp[0] = __nv_bfloat162(h0, h1); hp[1] = __nv_bfloat162(h2, h3);
    lp[0] = __nv_bfloat162(l0, l1); lp[1] = __nv_bfloat162(l2, l3);
}

// ---------------------------------------------------------------------------
// mma.sync split-bf16 GEMM (unchanged from R14: 2 CTAs/SM, 2-stage).
// ---------------------------------------------------------------------------
#define BKC 32
#define TILEB (128 * 40 * 2)
#define STAGEB (4 * TILEB)
#define STAGES 2
#define GT_SMEM (STAGES * STAGEB)          // 81920 B

__global__ __launch_bounds__(256, 2) void gemm_mma(
    const __nv_bfloat16* __restrict__ Ahi, const __nv_bfloat16* __restrict__ Alo,
    const __nv_bfloat16* __restrict__ Bhi, const __nv_bfloat16* __restrict__ Blo,
    float* __restrict__ C, int M, int N, int K)
{
    extern __shared__ char sm[];
    const uint32_t sb = smem_u32(sm);
    const int tid = threadIdx.x;
    const int wid = tid >> 5, lane = tid & 31;
    const int wm = (wid >> 2) * 64;
    const int wn = (wid & 3) * 32;
    const int rowBase = blockIdx.y * 128;
    const int colBase = blockIdx.x * 128;
    const int NC = K / BKC;

    const __nv_bfloat16* srcs[4] = {
        Ahi + (size_t)rowBase * K, Alo + (size_t)rowBase * K,
        Bhi + (size_t)colBase * K, Blo + (size_t)colBase * K };

    auto load_chunk = [&](int c) {
        uint32_t stb = sb + (uint32_t)(c & (STAGES - 1)) * STAGEB;
#pragma unroll
        for (int j = 0; j < 8; j++) {
            int idx = tid + j * 256;
            int t4 = idx >> 9;
            int e  = idx & 511;
            int r  = e >> 2, c4 = e & 3;
            uint32_t dst = stb + (uint32_t)t4 * TILEB + (uint32_t)(r * 80 + c4 * 16);
            cpa16(dst, srcs[t4] + (size_t)c * BKC + (size_t)r * K + c4 * 8);
        }
        cpa_commit();
    };

    const uint32_t aoff = (uint32_t)((lane & 15) * 80 + (lane >> 4) * 16);
    const uint32_t boff = (uint32_t)(((lane & 7) + 8 * (lane >> 4)) * 80 +
                                     ((lane >> 3) & 1) * 16);

    float acc[4][4][4];
#pragma unroll
    for (int mi = 0; mi < 4; mi++)
#pragma unroll
        for (int nj = 0; nj < 4; nj++)
#pragma unroll
            for (int e = 0; e < 4; e++) acc[mi][nj][e] = 0.0f;

    load_chunk(0);
    load_chunk(1);

    for (int c = 0; c < NC; c++) {
        cpa_wait<1>();
        __syncthreads();

        uint32_t stb = sb + (uint32_t)(c & (STAGES - 1)) * STAGEB;
        const uint32_t sAhi = stb, sAlo = stb + TILEB;
        const uint32_t sBhi = stb + 2 * TILEB, sBlo = stb + 3 * TILEB;

#pragma unroll
        for (int ks = 0; ks < 2; ks++) {
            uint32_t kb = (uint32_t)(32 * ks);
            uint32_t bhi[4][2], blo[4][2];
#pragma unroll
            for (int njp = 0; njp < 2; njp++) {
                uint32_t r4[4];
                uint32_t bo = (uint32_t)((wn + 16 * njp) * 80) + kb + boff;
                ldsm4(r4, sBhi + bo);
                bhi[2 * njp][0] = r4[0]; bhi[2 * njp][1] = r4[1];
                bhi[2 * njp + 1][0] = r4[2]; bhi[2 * njp + 1][1] = r4[3];
                ldsm4(r4, sBlo + bo);
                blo[2 * njp][0] = r4[0]; blo[2 * njp][1] = r4[1];
                blo[2 * njp + 1][0] = r4[2]; blo[2 * njp + 1][1] = r4[3];
            }
            uint32_t ahi[4][4], alo[4][4];
#pragma unroll
            for (int mi = 0; mi < 4; mi++) {
                uint32_t ao = (uint32_t)((wm + 16 * mi) * 80) + kb + aoff;
                ldsm4(ahi[mi], sAhi + ao);
                ldsm4(alo[mi], sAlo + ao);
            }
#pragma unroll
            for (int mi = 0; mi < 4; mi++)
#pragma unroll
                for (int nj = 0; nj < 4; nj++)
                    mma16816(acc[mi][nj], ahi[mi], bhi[nj]);
#pragma unroll
            for (int mi = 0; mi < 4; mi++)
#pragma unroll
                for (int nj = 0; nj < 4; nj++)
                    mma16816(acc[mi][nj], ahi[mi], blo[nj]);
#pragma unroll
            for (int mi = 0; mi < 4; mi++)
#pragma unroll
                for (int nj = 0; nj < 4; nj++)
                    mma16816(acc[mi][nj], alo[mi], bhi[nj]);
        }
        __syncthreads();
        if (c + 2 < NC) load_chunk(c + 2);
        else cpa_commit();
    }

    const int r0 = rowBase + wm + (lane >> 2);
    const int c0 = colBase + wn + 2 * (lane & 3);
#pragma unroll
    for (int mi = 0; mi < 4; mi++) {
#pragma unroll
        for (int nj = 0; nj < 4; nj++) {
            float* p0 = C + (size_t)(r0 + 16 * mi) * N + c0 + 8 * nj;
            float* p1 = p0 + (size_t)8 * N;
            *(float2*)p0 = make_float2(acc[mi][nj][0], acc[mi][nj][1]);
            *(float2*)p1 = make_float2(acc[mi][nj][2], acc[mi][nj][3]);
        }
    }
}

// ---------------------------------------------------------------------------
// Fused RMSNorm + RoPE + hi/lo split (strided QKV input).
// ---------------------------------------------------------------------------
__global__ __launch_bounds__(128) void norm_rope_split(
    const float* __restrict__ src, int srcOff,
    __nv_bfloat16* __restrict__ hi, __nv_bfloat16* __restrict__ lo,
    const float* __restrict__ w,
    const float* __restrict__ cs, const float* __restrict__ sn, int nh)
{
    const int row = blockIdx.x;
    const int m = row / nh, h = row - m * nh;
    const int s = m % S_;
    const int i = threadIdx.x;
    const float* p = src + (size_t)m * NQKV + srcOff + h * HD_;
    float v = p[i];
    float ss = v * v;
#pragma unroll
    for (int o = 16; o; o >>= 1) ss += __shfl_xor_sync(0xffffffff, ss, o);
    __shared__ float wsum[4];
    __shared__ float nbuf[HD_];
    if ((i & 31) == 0) wsum[i >> 5] = ss;
    __syncthreads();
    float tot = wsum[0] + wsum[1] + wsum[2] + wsum[3];
    float rstd = rsqrtf(tot * (1.0f / HD_) + 1e-5f);
    float n = v * rstd * w[i];
    nbuf[i] = n;
    __syncthreads();
    float rot = (i < 64) ? -nbuf[i + 64] : nbuf[i - 64];
    float outv = n * cs[s * HD_ + i] + rot * sn[s * HD_ + i];
    __nv_bfloat16 hb = __float2bfloat16(outv);
    __nv_bfloat16 lb = __float2bfloat16(outv - __bfloat162float(hb));
    hi[(size_t)row * HD_ + i] = hb;
    lo[(size_t)row * HD_ + i] = lb;
}

// ---------------------------------------------------------------------------
// Strided split for V columns of QKV buffer.
// ---------------------------------------------------------------------------
__global__ __launch_bounds__(256) void split_v(const float* __restrict__ src,
                                               __nv_bfloat16* __restrict__ hi,
                                               __nv_bfloat16* __restrict__ lo) {
    int i = blockIdx.x * 256 + threadIdx.x;
    int m = i >> 7, c = i & 127;
    float4 v = *(const float4*)(src + (size_t)m * NQKV + 2560 + c * 4);
    __nv_bfloat16 h0 = __float2bfloat16(v.x), h1 = __float2bfloat16(v.y);
    __nv_bfloat16 h2 = __float2bfloat16(v.z), h3 = __float2bfloat16(v.w);
    __nv_bfloat16 l0 = __float2bfloat16(v.x - __bfloat162float(h0));
    __nv_bfloat16 l1 = __float2bfloat16(v.y - __bfloat162float(h1));
    __nv_bfloat16 l2 = __float2bfloat16(v.z - __bfloat162float(h2));
    __nv_bfloat16 l3 = __float2bfloat16(v.w - __bfloat162float(h3));
    size_t o = (size_t)m * 512 + c * 4;
    __nv_bfloat162* hp = (__nv_bfloat162*)(hi + o);
    __nv_bfloat162* lp = (__nv_bfloat162*)(lo + o);
    hp[0] = __nv_bfloat162(h0, h1); hp[1] = __nv_bfloat162(h2, h3);
    lp[0] = __nv_bfloat162(l0, l1); lp[1] = __nv_bfloat162(l2, l3);
}

// ---------------------------------------------------------------------------
// mma.sync split-bf16 causal GQA flash attention, 2 CTAs/SM version.
// BQ=64, BKV=64, HD=128. 4 warps x 16 q-rows. Single-buffered KV tile;
// cross-CTA overlap (2 CTAs/SM) hides the load phase.
// Smem: Q hi/lo 34816 + KV 69632 = 104448 B -> 2 CTAs/SM.
// ---------------------------------------------------------------------------
#define FA_ROWB 272
#define FA_QT  (64 * FA_ROWB)               // 17408 B per Q tile
#define FA_KVT (64 * FA_ROWB)               // 17408 B per KV tile
#define FA_SMEM (2 * FA_QT + 4 * FA_KVT)    // 104448 B

__global__ __launch_bounds__(128, 2) void flash_mma(
    const __nv_bfloat16* __restrict__ qh, const __nv_bfloat16* __restrict__ ql,
    const __nv_bfloat16* __restrict__ kh, const __nv_bfloat16* __restrict__ kl,
    const __nv_bfloat16* __restrict__ vh, const __nv_bfloat16* __restrict__ vl,
    __nv_bfloat16* __restrict__ ch, __nv_bfloat16* __restrict__ cl)
{
    extern __shared__ char sm[];
    const uint32_t sb  = smem_u32(sm);
    const uint32_t sQh = sb, sQl = sb + FA_QT;
    const uint32_t sKh = sb + 2 * FA_QT;
    const uint32_t sKl = sKh + FA_KVT;
    const uint32_t sVh = sKl + FA_KVT;
    const uint32_t sVl = sVh + FA_KVT;

    const int b = blockIdx.z, head = blockIdx.y;
    const int qt = gridDim.x - 1 - blockIdx.x;     // big tiles first
    const int q0 = qt * 64;
    const int kvh = head / G_;
    const int tid = threadIdx.x, wid = tid >> 5, lane = tid & 31;
    const int m0 = wid * 16;
    const float scale = 0.08838834764831845f;

    // ---- Q tile (hi/lo) via cp.async: 2 x 64x128 bf16 = 2048 chunks ----
    {
        const __nv_bfloat16* srcs[2] = { qh, ql };
#pragma unroll
        for (int j = 0; j < 16; j++) {
            int idx = tid + j * 128;
            int t = idx >> 10;
            int e = idx & 1023;
            int r = e >> 4, c = e & 15;
            uint32_t dst = (t ? sQl : sQh) + (uint32_t)(r * FA_ROWB + c * 16);
            cpa16(dst, srcs[t] + ((size_t)(b * S_ + q0 + r) * H_ + head) * HD_ + c * 8);
        }
    }
    auto load_kv = [&](int kt) {
        const __nv_bfloat16* srcs[4] = { kh, kl, vh, vl };
        const uint32_t dsts[4] = { sKh, sKl, sVh, sVl };
#pragma unroll
        for (int j = 0; j < 32; j++) {
            int idx = tid + j * 128;
            int t4 = idx >> 10;
            int e = idx & 1023;
            int r = e >> 4, c = e & 15;
            uint32_t dst = dsts[t4] + (uint32_t)(r * FA_ROWB + c * 16);
            cpa16(dst, srcs[t4] + ((size_t)(b * S_ + kt * 64 + r) * KV_ + kvh) * HD_ + c * 8);
        }
        cpa_commit();
    };

    const uint32_t aoff = (uint32_t)((lane & 15) * FA_ROWB + (lane >> 4) * 16);
    const uint32_t boff = (uint32_t)(((lane & 7) + 8 * (lane >> 4)) * FA_ROWB +
                                     ((lane >> 3) & 1) * 16);

    float oacc[16][4];
#pragma unroll
    for (int nf = 0; nf < 16; nf++)
#pragma unroll
        for (int e = 0; e < 4; e++) oacc[nf][e] = 0.0f;
    float mold[2] = { -1e30f, -1e30f }, lsum[2] = { 0.0f, 0.0f };

    const int nkv = qt + 1;
    for (int kt = 0; kt < nkv; kt++) {
        load_kv(kt);
        cpa_wait<0>();                   // KV tile (and Q on first iter) landed
        __syncthreads();

        // ---- S = Q K^T (term-major) ----
        float sacc[8][4];
#pragma unroll
        for (int nf = 0; nf < 8; nf++)
#pragma unroll
            for (int e = 0; e < 4; e++) sacc[nf][e] = 0.0f;
#pragma unroll
        for (int ks = 0; ks < 8; ks++) {
            uint32_t bh[8][2], bl[8][2];
#pragma unroll
            for (int njp = 0; njp < 4; njp++) {
                uint32_t r4[4];
                uint32_t bo = (uint32_t)(16 * njp * FA_ROWB) + ks * 32 + boff;
                ldsm4(r4, sKh + bo);
                bh[2 * njp][0] = r4[0]; bh[2 * njp][1] = r4[1];
                bh[2 * njp + 1][0] = r4[2]; bh[2 * njp + 1][1] = r4[3];
                ldsm4(r4, sKl + bo);
                bl[2 * njp][0] = r4[0]; bl[2 * njp][1] = r4[1];
                bl[2 * njp + 1][0] = r4[2]; bl[2 * njp + 1][1] = r4[3];
            }
            uint32_t ah[4], al[4];
            uint32_t ao = (uint32_t)(m0 * FA_ROWB) + ks * 32 + aoff;
            ldsm4(ah, sQh + ao);
            ldsm4(al, sQl + ao);
#pragma unroll
            for (int nf = 0; nf < 8; nf++) mma16816(sacc[nf], ah, bh[nf]);
#pragma unroll
            for (int nf = 0; nf < 8; nf++) mma16816(sacc[nf], ah, bl[nf]);
#pragma unroll
            for (int nf = 0; nf < 8; nf++) mma16816(sacc[nf], al, bh[nf]);
        }

        // ---- online softmax ----
        const bool diag = (kt == qt);
        float alpha[2];
#pragma unroll
        for (int hh = 0; hh < 2; hh++) {
            int rowg = q0 + m0 + (lane >> 2) + 8 * hh;
            float mx = mold[hh];
#pragma unroll
            for (int nf = 0; nf < 8; nf++)
#pragma unroll
                for (int e = 0; e < 2; e++) {
                    float v = sacc[nf][2 * hh + e] * scale;
                    if (diag) {
                        int colg = kt * 64 + nf * 8 + 2 * (lane & 3) + e;
                        if (colg > rowg) v = -1e30f;
                    }
                    sacc[nf][2 * hh + e] = v;
                    mx = fmaxf(mx, v);
                }
            mx = fmaxf(mx, __shfl_xor_sync(0xffffffffu, mx, 1));
            mx = fmaxf(mx, __shfl_xor_sync(0xffffffffu, mx, 2));
            float al = __expf(mold[hh] - mx);
            float s = 0.0f;
#pragma unroll
            for (int nf = 0; nf < 8; nf++)
#pragma unroll
                for (int e = 0; e < 2; e++) {
                    float p = __expf(sacc[nf][2 * hh + e] - mx);
                    sacc[nf][2 * hh + e] = p;
                    s += p;
                }
            s += __shfl_xor_sync(0xffffffffu, s, 1);
            s += __shfl_xor_sync(0xffffffffu, s, 2);
            mold[hh] = mx;
            lsum[hh] = lsum[hh] * al + s;
            alpha[hh] = al;
        }

        uint32_t aPh[4][4], aPl[4][4];
#pragma unroll
        for (int kc = 0; kc < 4; kc++) {
            split2(sacc[2 * kc][0],     sacc[2 * kc][1],     aPh[kc][0], aPl[kc][0]);
            split2(sacc[2 * kc][2],     sacc[2 * kc][3],     aPh[kc][1], aPl[kc][1]);
            split2(sacc[2 * kc + 1][0], sacc[2 * kc + 1][1], aPh[kc][2], aPl[kc][2]);
            split2(sacc[2 * kc + 1][2], sacc[2 * kc + 1][3], aPh[kc][3], aPl[kc][3]);
        }

#pragma unroll
        for (int nf = 0; nf < 16; nf++) {
            oacc[nf][0] *= alpha[0]; oacc[nf][1] *= alpha[0];
            oacc[nf][2] *= alpha[1]; oacc[nf][3] *= alpha[1];
        }

        // ---- O += P V (term-major, dq-pair unroll) ----
#pragma unroll
        for (int kc = 0; kc < 4; kc++) {
#pragma unroll
            for (int dq = 0; dq < 4; dq++) {
                uint32_t r4[4];
                uint32_t vo0 = (uint32_t)(kc * 16 * FA_ROWB) + (2 * dq) * 32 + aoff;
                uint32_t bh[4][2], bl[4][2];
                ldsm4t(r4, sVh + vo0);
                bh[0][0] = r4[0]; bh[0][1] = r4[1]; bh[1][0] = r4[2]; bh[1][1] = r4[3];
                ldsm4t(r4, sVh + vo0 + 32);
                bh[2][0] = r4[0]; bh[2][1] = r4[1]; bh[3][0] = r4[2]; bh[3][1] = r4[3];
                ldsm4t(r4, sVl + vo0);
                bl[0][0] = r4[0]; bl[0][1] = r4[1]; bl[1][0] = r4[2]; bl[1][1] = r4[3];
                ldsm4t(r4, sVl + vo0 + 32);
                bl[2][0] = r4[0]; bl[2][1] = r4[1]; bl[3][0] = r4[2]; bl[3][1] = r4[3];
#pragma unroll
                for (int u = 0; u < 4; u++) mma16816(oacc[4 * dq + u], aPh[kc], bh[u]);
#pragma unroll
                for (int u = 0; u < 4; u++) mma16816(oacc[4 * dq + u], aPh[kc], bl[u]);
#pragma unroll
                for (int u = 0; u < 4; u++) mma16816(oacc[4 * dq + u], aPl[kc], bh[u]);
            }
        }
        __syncthreads();                 // all warps done before next overwrite
    }

    // ---- epilogue: normalize, split to bf16 hi/lo, store ----
    float linv[2] = { 1.0f / lsum[0], 1.0f / lsum[1] };
#pragma unroll
    for (int nf = 0; nf < 16; nf++) {
#pragma unroll
        for (int hh = 0; hh < 2; hh++) {
            int rq = q0 + m0 + (lane >> 2) + 8 * hh;
            int col = head * HD_ + nf * 8 + 2 * (lane & 3);
            float v0 = oacc[nf][2 * hh] * linv[hh];
            float v1 = oacc[nf][2 * hh + 1] * linv[hh];
            uint32_t hi, lo;
            split2(v0, v1, hi, lo);
            size_t o = (size_t)(b * S_ + rq) * D_ + col;
            *(uint32_t*)(ch + o) = hi;
            *(uint32_t*)(cl + o) = lo;
        }
    }
}

// ---------------------------------------------------------------------------
extern "C" void kernel_launch(void* const* d_in, const int* in_sizes, int n_in,
                              void* d_out, int out_size) {
    const float* x    = (const float*)d_in[0];
    const float* cs   = (const float*)d_in[2];
    const float* sn   = (const float*)d_in[3];
    const float* W_q  = (const float*)d_in[4];
    const float* W_k  = (const float*)d_in[5];
    const float* W_v  = (const float*)d_in[6];
    const float* W_o  = (const float*)d_in[7];
    const float* qnw  = (const float*)d_in[8];
    const float* knw  = (const float*)d_in[9];
    float* out = (float*)d_out;

    float* qkv;
    cudaGetSymbolAddress((void**)&qkv, g_qkv);
    __nv_bfloat16 *xh, *xl, *ch, *cl, *wqkvh, *wqkvl, *woh, *wol;
    __nv_bfloat16 *qhh, *qll, *khh, *kll, *vhh, *vll;
    cudaGetSymbolAddress((void**)&xh,    g_x_hi);    cudaGetSymbolAddress((void**)&xl,    g_x_lo);
    cudaGetSymbolAddress((void**)&ch,    g_ctx_hi);  cudaGetSymbolAddress((void**)&cl,    g_ctx_lo);
    cudaGetSymbolAddress((void**)&wqkvh, g_wqkv_hi); cudaGetSymbolAddress((void**)&wqkvl, g_wqkv_lo);
    cudaGetSymbolAddress((void**)&woh,   g_wo_hi);   cudaGetSymbolAddress((void**)&wol,   g_wo_lo);
    cudaGetSymbolAddress((void**)&qhh,   g_qhi);     cudaGetSymbolAddress((void**)&qll,   g_qlo);
    cudaGetSymbolAddress((void**)&khh,   g_khi);     cudaGetSymbolAddress((void**)&kll,   g_klo);
    cudaGetSymbolAddress((void**)&vhh,   g_vhi);     cudaGetSymbolAddress((void**)&vll,   g_vlo);

    static int attr_set = 0;
    if (!attr_set) {
        cudaFuncSetAttribute(gemm_mma, cudaFuncAttributeMaxDynamicSharedMemorySize, GT_SMEM);
        cudaFuncSetAttribute(flash_mma, cudaFuncAttributeMaxDynamicSharedMemorySize, FA_SMEM);
        attr_set = 1;
    }

    const int M = B_ * S_;              // 4096
    const int NXY = M * D_ / 4;
    const int NW  = D_ * D_ / 4;
    const int NKW = KV_ * HD_ * D_ / 4;

    split_bf16<<<(NXY + 255) / 256, 256>>>(x,   xh,  xl,  NXY);
    split_bf16<<<(NW  + 255) / 256, 256>>>(W_q, wqkvh,                           wqkvl,                           NW);
    split_bf16<<<(NKW + 255) / 256, 256>>>(W_k, wqkvh + (size_t)D_ * D_,         wqkvl + (size_t)D_ * D_,         NKW);
    split_bf16<<<(NKW + 255) / 256, 256>>>(W_v, wqkvh + (size_t)(D_ + 512) * D_, wqkvl + (size_t)(D_ + 512) * D_, NKW);
    split_bf16<<<(NW  + 255) / 256, 256>>>(W_o, woh, wol, NW);

    // Fused QKV projection
    {
        dim3 g(NQKV / 128, M / 128);
        gemm_mma<<<g, 256, GT_SMEM>>>(xh, xl, wqkvh, wqkvl, qkv, M, NQKV, D_);
    }

    // RMSNorm + RoPE + split (q, k); plain split (v)
    norm_rope_split<<<M * H_, 128>>>(qkv, 0,    qhh, qll, qnw, cs, sn, H_);
    norm_rope_split<<<M * KV_, 128>>>(qkv, 2048, khh, kll, knw, cs, sn, KV_);
    split_v<<<M * 128 / 256, 256>>>(qkv, vhh, vll);

    // Attention (BQ=64, 2 CTAs/SM)
    {
        dim3 g(S_ / 64, H_, B_);
        flash_mma<<<g, 128, FA_SMEM>>>(qhh, qll, khh, kll, vhh, vll, ch, cl);
    }

    // Output projection
    {
        dim3 go(D_ / 128, M / 128);
        gemm_mma<<<go, 256, GT_SMEM>>>(ch, cl, woh, wol, out, M, D_, D_);
    }
}